// round 15
// baseline (speedup 1.0000x reference)
#include <cuda_runtime.h>
#include <cuda_bf16.h>
#include <math.h>
#include <math_constants.h>
#include <cstdint>

// Problem constants
#define B_   2
#define S_   2048
#define HID_ 2048
#define NH_  16
#define NKV_ 4
#define HD_  128
#define ROWS_ (B_ * S_)          // 4096

// Q pre-scale: 1/sqrt(128) * log2(e)
#define QSC ((float)(0.08838834764831845 * 1.4426950408889634))

// ---------------- scratch (device globals; no allocation allowed) ----------
__device__ float g_v[ROWS_ * NKV_ * HD_];    // fp32 V (pre-transpose)
__device__ float g_cos[S_ * 64];
__device__ float g_sin[S_ * 64];

// bf16 split operands
__device__ __nv_bfloat16 g_hs_h[ROWS_ * HID_];
__device__ __nv_bfloat16 g_hs_l[ROWS_ * HID_];
__device__ __nv_bfloat16 g_at_h[ROWS_ * HID_];
__device__ __nv_bfloat16 g_at_l[ROWS_ * HID_];
__device__ __nv_bfloat16 g_w3_h[3072 * 2048];  // [Q|K|V] weights, [N,K]
__device__ __nv_bfloat16 g_w3_l[3072 * 2048];
__device__ __nv_bfloat16 g_ow_h[2048 * 2048];
__device__ __nv_bfloat16 g_ow_l[2048 * 2048];

__device__ __nv_bfloat16 g_qh[B_ * NH_ * S_ * HD_];   // [b][h][s][d]
__device__ __nv_bfloat16 g_ql[B_ * NH_ * S_ * HD_];
__device__ __nv_bfloat16 g_kh[B_ * NKV_ * S_ * HD_];  // [b][kvh][s][d]
__device__ __nv_bfloat16 g_kl[B_ * NKV_ * S_ * HD_];
__device__ __nv_bfloat16 g_vh[B_ * NKV_ * HD_ * S_];  // [b][kvh][d][s]
__device__ __nv_bfloat16 g_vl[B_ * NKV_ * HD_ * S_];

// ====================== helpers =============================================
__device__ __forceinline__ uint32_t smem_u32(const void* p) {
    uint32_t r;
    asm("{ .reg .u64 t; cvta.to.shared.u64 t, %1; cvt.u32.u64 %0, t; }"
        : "=r"(r) : "l"(p));
    return r;
}

__device__ __forceinline__ void cp16(uint32_t dst, const void* src) {
    asm volatile("cp.async.cg.shared.global [%0], [%1], 16;"
                 :: "r"(dst), "l"(src) : "memory");
}

__device__ __forceinline__ float ex2(float x) {
    float r;
    asm("ex2.approx.f32 %0, %1;" : "=f"(r) : "f"(x));
    return r;
}

__device__ __forceinline__ void mma_bf16(float c[4], uint32_t a0, uint32_t a1,
                                         uint32_t a2, uint32_t a3,
                                         uint32_t b0, uint32_t b1) {
    asm volatile(
        "mma.sync.aligned.m16n8k16.row.col.f32.bf16.bf16.f32 "
        "{%0,%1,%2,%3}, {%4,%5,%6,%7}, {%8,%9}, {%0,%1,%2,%3};"
        : "+f"(c[0]), "+f"(c[1]), "+f"(c[2]), "+f"(c[3])
        : "r"(a0), "r"(a1), "r"(a2), "r"(a3), "r"(b0), "r"(b1));
}

__device__ __forceinline__ void ldsm4(uint32_t a[4], uint32_t addr) {
    asm volatile("ldmatrix.sync.aligned.m8n8.x4.shared.b16 {%0,%1,%2,%3}, [%4];"
                 : "=r"(a[0]), "=r"(a[1]), "=r"(a[2]), "=r"(a[3]) : "r"(addr));
}

__device__ __forceinline__ void split_pack(float x0, float x1,
                                           uint32_t& hi, uint32_t& lo) {
    uint32_t h;
    asm("cvt.rn.bf16x2.f32 %0, %1, %2;" : "=r"(h) : "f"(x1), "f"(x0));
    float h0 = __uint_as_float(h << 16);
    float h1 = __uint_as_float(h & 0xFFFF0000u);
    float r0 = x0 - h0, r1 = x1 - h1;
    uint32_t l;
    asm("cvt.rn.bf16x2.f32 %0, %1, %2;" : "=r"(l) : "f"(r1), "f"(r0));
    hi = h;
    lo = l;
}

// ================= HMMA split-bf16 GEMM (fused epilogues) ===================
// C[M,N] = A[M,K] @ Bt[N,K]^T. 3-stage cp.async pipeline, pitch 80B, 2 CTAs/SM.
// BM=64 BN=128 BK=32, 256 threads (8 warps 2x4), warp tile 32x32.
// Prefetch issued BEFORE the compute burst (overlaps MMAs).
// MODE 0: fp32 out to C. MODE 3: fused QKV epilogue by n0.
#define HG_P    80
#define HG_SA_L 5120
#define HG_SB_H 10240
#define HG_SB_L 20480
#define HG_STAGE 30720
#define HG_SMEM (3 * HG_STAGE)   // 92160 per CTA -> 2 CTAs/SM

template <int MODE>
__global__ __launch_bounds__(256, 2) void hgemm_kernel(
    const __nv_bfloat16* __restrict__ Ah, const __nv_bfloat16* __restrict__ Al,
    const __nv_bfloat16* __restrict__ Bh, const __nv_bfloat16* __restrict__ Bl,
    const float* __restrict__ qb, const float* __restrict__ kb,
    const float* __restrict__ vb, float* __restrict__ C,
    uint32_t* __restrict__ OH, uint32_t* __restrict__ OL,
    uint32_t* __restrict__ OH2, uint32_t* __restrict__ OL2,
    const float* __restrict__ cs, const float* __restrict__ sn,
    int M, int N, int K) {
    extern __shared__ __align__(16) char smc[];
    uint32_t sb = smem_u32(smc);
    int tid = threadIdx.x, wid = tid >> 5, lane = tid & 31;
    int warp_m = wid >> 2, warp_n = wid & 3;
    int m0 = blockIdx.y * 64, n0 = blockIdx.x * 128;
    int g = lane >> 2, t = lane & 3;

    int r8 = lane & 7, sel = lane >> 3;
    uint32_t aoff = (uint32_t)((warp_m * 32 + (sel & 1) * 8 + r8) * HG_P +
                               (sel >> 1) * 16);
    uint32_t boff = (uint32_t)((warp_n * 32 + ((lane >> 4) & 1) * 8 + r8) * HG_P +
                               ((lane >> 3) & 1) * 16);

    auto load_stage = [&](int k0, int stg) {
        uint32_t st = sb + stg * HG_STAGE;
        {
            int row = tid >> 2, seg = tid & 3;
            uint32_t so = row * HG_P + seg * 16;
            size_t ga = (size_t)(m0 + row) * K + k0 + seg * 8;
            cp16(st + so, Ah + ga);
            cp16(st + HG_SA_L + so, Al + ga);
        }
#pragma unroll
        for (int i = 0; i < 2; i++) {
            int idx = tid + i * 256;
            int row = idx >> 2, seg = idx & 3;
            uint32_t so = row * HG_P + seg * 16;
            size_t gb = (size_t)(n0 + row) * K + k0 + seg * 8;
            cp16(st + HG_SB_H + so, Bh + gb);
            cp16(st + HG_SB_L + so, Bl + gb);
        }
        asm volatile("cp.async.commit_group;" ::: "memory");
    };

    float acc[2][4][4];
#pragma unroll
    for (int i = 0; i < 2; i++)
#pragma unroll
        for (int j = 0; j < 4; j++)
#pragma unroll
            for (int x = 0; x < 4; x++) acc[i][j][x] = 0.0f;

    const int niter = K / 32;
    load_stage(0, 0);
    load_stage(32, 1);

    for (int it = 0; it < niter; it++) {
        if (it < niter - 1)
            asm volatile("cp.async.wait_group 1;" ::: "memory");
        else
            asm volatile("cp.async.wait_group 0;" ::: "memory");
        __syncthreads();
        // Prefetch BEFORE compute: stage (it+2)%3 == (it-1)%3, which the
        // barrier above guarantees all warps finished reading.
        if (it + 2 < niter) load_stage((it + 2) * 32, (it + 2) % 3);
        uint32_t st = sb + (it % 3) * HG_STAGE;

#pragma unroll
        for (int kc = 0; kc < 2; kc++) {
            uint32_t ah[2][4], al[2][4];
#pragma unroll
            for (int fm = 0; fm < 2; fm++) {
                ldsm4(ah[fm], st + aoff + fm * (16 * HG_P) + kc * 32);
                ldsm4(al[fm], st + HG_SA_L + aoff + fm * (16 * HG_P) + kc * 32);
            }
            uint32_t bh4[2][4], bl4[2][4];
#pragma unroll
            for (int fnp = 0; fnp < 2; fnp++) {
                uint32_t bo = boff + fnp * (16 * HG_P) + kc * 32;
                ldsm4(bh4[fnp], st + HG_SB_H + bo);
                ldsm4(bl4[fnp], st + HG_SB_L + bo);
            }
#pragma unroll
            for (int fm = 0; fm < 2; fm++)
#pragma unroll
                for (int fnp = 0; fnp < 2; fnp++) {
                    mma_bf16(acc[fm][2 * fnp], ah[fm][0], ah[fm][1], ah[fm][2],
                             ah[fm][3], bh4[fnp][0], bh4[fnp][1]);
                    mma_bf16(acc[fm][2 * fnp + 1], ah[fm][0], ah[fm][1],
                             ah[fm][2], ah[fm][3], bh4[fnp][2], bh4[fnp][3]);
                }
#pragma unroll
            for (int fm = 0; fm < 2; fm++)
#pragma unroll
                for (int fnp = 0; fnp < 2; fnp++) {
                    mma_bf16(acc[fm][2 * fnp], ah[fm][0], ah[fm][1], ah[fm][2],
                             ah[fm][3], bl4[fnp][0], bl4[fnp][1]);
                    mma_bf16(acc[fm][2 * fnp + 1], ah[fm][0], ah[fm][1],
                             ah[fm][2], ah[fm][3], bl4[fnp][2], bl4[fnp][3]);
                }
#pragma unroll
            for (int fm = 0; fm < 2; fm++)
#pragma unroll
                for (int fnp = 0; fnp < 2; fnp++) {
                    mma_bf16(acc[fm][2 * fnp], al[fm][0], al[fm][1], al[fm][2],
                             al[fm][3], bh4[fnp][0], bh4[fnp][1]);
                    mma_bf16(acc[fm][2 * fnp + 1], al[fm][0], al[fm][1],
                             al[fm][2], al[fm][3], bh4[fnp][2], bh4[fnp][3]);
                }
        }
    }

    // epilogue
#pragma unroll
    for (int fm = 0; fm < 2; fm++) {
        int row0 = m0 + warp_m * 32 + fm * 16 + g;
#pragma unroll
        for (int fn = 0; fn < 4; fn++) {
            int col = n0 + warp_n * 32 + fn * 8 + 2 * t;
            if (MODE == 0) {
                float2 v0, v1;
                v0.x = acc[fm][fn][0];
                v0.y = acc[fm][fn][1];
                v1.x = acc[fm][fn][2];
                v1.y = acc[fm][fn][3];
                *(float2*)(C + (size_t)row0 * N + col) = v0;
                *(float2*)(C + (size_t)(row0 + 8) * N + col) = v1;
            } else if (n0 < 2048) {
                float2 bb = *(const float2*)(qb + col);
                float vx[2] = {acc[fm][fn][0] + bb.x, acc[fm][fn][2] + bb.x};
                float vy[2] = {acc[fm][fn][1] + bb.y, acc[fm][fn][3] + bb.y};
                int hh = col >> 7;
                int p = (col & 127) >> 1;
#pragma unroll
                for (int rr = 0; rr < 2; rr++) {
                    int row = row0 + rr * 8;
                    int s = row & (S_ - 1);
                    int bb_ = row >> 11;
                    float cv = cs[s * 64 + p];
                    float sv = sn[s * 64 + p];
                    float o1 = (vx[rr] * cv - vy[rr] * sv) * QSC;
                    float o2 = (vx[rr] * sv + vy[rr] * cv) * QSC;
                    uint32_t hi, lo;
                    split_pack(o1, o2, hi, lo);
                    size_t wi = (((size_t)bb_ * NH_ + hh) * S_ + s) * 64 + p;
                    OH[wi] = hi;
                    OL[wi] = lo;
                }
            } else if (n0 < 2560) {
                int c2 = col - 2048;
                float2 bb = *(const float2*)(kb + c2);
                float vx[2] = {acc[fm][fn][0] + bb.x, acc[fm][fn][2] + bb.x};
                float vy[2] = {acc[fm][fn][1] + bb.y, acc[fm][fn][3] + bb.y};
                int hh = c2 >> 7;
                int p = (c2 & 127) >> 1;
#pragma unroll
                for (int rr = 0; rr < 2; rr++) {
                    int row = row0 + rr * 8;
                    int s = row & (S_ - 1);
                    int bb_ = row >> 11;
                    float cv = cs[s * 64 + p];
                    float sv = sn[s * 64 + p];
                    float o1 = vx[rr] * cv - vy[rr] * sv;
                    float o2 = vx[rr] * sv + vy[rr] * cv;
                    uint32_t hi, lo;
                    split_pack(o1, o2, hi, lo);
                    size_t wi = (((size_t)bb_ * NKV_ + hh) * S_ + s) * 64 + p;
                    OH2[wi] = hi;
                    OL2[wi] = lo;
                }
            } else {
                int c2 = col - 2560;
                float2 bb = *(const float2*)(vb + c2);
                float2 v0, v1;
                v0.x = acc[fm][fn][0] + bb.x;
                v0.y = acc[fm][fn][1] + bb.y;
                v1.x = acc[fm][fn][2] + bb.x;
                v1.y = acc[fm][fn][3] + bb.y;
                *(float2*)(C + (size_t)row0 * 512 + c2) = v0;
                *(float2*)(C + (size_t)(row0 + 8) * 512 + c2) = v1;
            }
        }
    }
}

// ---------------- conversion kernels ----------------------------------------
__global__ void split_hs_rope_kernel(const float* __restrict__ x,
                                     __nv_bfloat16* __restrict__ h,
                                     __nv_bfloat16* __restrict__ l, int n4,
                                     float* __restrict__ cs,
                                     float* __restrict__ sn) {
    int i = blockIdx.x * blockDim.x + threadIdx.x;
    if (blockIdx.x < 512) {
        int idx = i;
        int s = idx >> 6;
        int p = idx & 63;
        double freq = exp(-((double)(2 * p) / (double)HD_) * log(10000.0));
        double ang = (double)s * freq;
        double sv, cv;
        sincos(ang, &sv, &cv);
        cs[idx] = (float)cv;
        sn[idx] = (float)sv;
    }
    if (i >= n4) return;
    float4 v = ((const float4*)x)[i];
    uint32_t h0, l0, h1, l1;
    split_pack(v.x, v.y, h0, l0);
    split_pack(v.z, v.w, h1, l1);
    ((uint32_t*)h)[i * 2 + 0] = h0;
    ((uint32_t*)h)[i * 2 + 1] = h1;
    ((uint32_t*)l)[i * 2 + 0] = l0;
    ((uint32_t*)l)[i * 2 + 1] = l1;
}

// Fused QKV weight transpose: q_w/k_w/v_w [K,N] fp32 -> W3h/W3l [3072][2048]
__global__ void transpose_w3_kernel(const float* __restrict__ qw,
                                    const float* __restrict__ kw,
                                    const float* __restrict__ vw,
                                    __nv_bfloat16* __restrict__ Th,
                                    __nv_bfloat16* __restrict__ Tl) {
    __shared__ float tshm[32][33];
    int colg = blockIdx.x * 32;
    int k0 = blockIdx.y * 32;
    const float* W;
    int N, n0;
    if (colg < 2048) {
        W = qw; N = 2048; n0 = colg;
    } else if (colg < 2560) {
        W = kw; N = 512; n0 = colg - 2048;
    } else {
        W = vw; N = 512; n0 = colg - 2560;
    }
    int tx = threadIdx.x, ty = threadIdx.y;
#pragma unroll
    for (int i = 0; i < 32; i += 8)
        tshm[ty + i][tx] = W[(size_t)(k0 + ty + i) * N + n0 + tx];
    __syncthreads();
#pragma unroll
    for (int i = 0; i < 32; i += 8) {
        int n = colg + ty + i, k = k0 + tx;
        float v = tshm[tx][ty + i];
        __nv_bfloat16 hb = __float2bfloat16(v);
        Th[(size_t)n * 2048 + k] = hb;
        Tl[(size_t)n * 2048 + k] = __float2bfloat16(v - __bfloat162float(hb));
    }
}

// O weight transpose: [K,N] fp32 -> [N,K] bf16 hi/lo
__global__ void transpose_split_kernel(const float* __restrict__ W,
                                       __nv_bfloat16* __restrict__ Th,
                                       __nv_bfloat16* __restrict__ Tl,
                                       int K, int N) {
    __shared__ float tshm[32][33];
    int n0 = blockIdx.x * 32, k0 = blockIdx.y * 32;
    int tx = threadIdx.x, ty = threadIdx.y;
#pragma unroll
    for (int i = 0; i < 32; i += 8)
        tshm[ty + i][tx] = W[(size_t)(k0 + ty + i) * N + n0 + tx];
    __syncthreads();
#pragma unroll
    for (int i = 0; i < 32; i += 8) {
        int n = n0 + ty + i, k = k0 + tx;
        float v = tshm[tx][ty + i];
        __nv_bfloat16 hb = __float2bfloat16(v);
        Th[(size_t)n * K + k] = hb;
        Tl[(size_t)n * K + k] = __float2bfloat16(v - __bfloat162float(hb));
    }
}

// V: fp32 -> bf16 hi/lo TRANSPOSED [b][kvh][d][s]
__global__ void split_vt_kernel(const float* __restrict__ v,
                                __nv_bfloat16* __restrict__ vh,
                                __nv_bfloat16* __restrict__ vl) {
    __shared__ float tshm[32][33];
    int bk = blockIdx.z;
    int b = bk >> 2, kvh = bk & 3;
    int s0 = blockIdx.x * 32, d0 = blockIdx.y * 32;
    int tx = threadIdx.x, ty = threadIdx.y;
#pragma unroll
    for (int i = 0; i < 32; i += 8)
        tshm[ty + i][tx] = v[((size_t)(b * S_ + s0 + ty + i)) * 512 + kvh * 128 + d0 + tx];
    __syncthreads();
#pragma unroll
    for (int i = 0; i < 32; i += 8) {
        float x = tshm[tx][ty + i];
        __nv_bfloat16 hb = __float2bfloat16(x);
        size_t o = ((size_t)bk * 128 + d0 + ty + i) * (size_t)S_ + s0 + tx;
        vh[o] = hb;
        vl[o] = __float2bfloat16(x - __bfloat162float(hb));
    }
}

// ---------------- Flash attention (HMMA, bf16 3-term split, ldmatrix) -------
#define FL_QL 0
#define FL_QH 34816
#define FL_STG 69632
#define FL_STG_BYTES 71680
#define FL_KL 17408
#define FL_VH 34816
#define FL_VL 53248
#define FL_SMEM (FL_STG + 2 * FL_STG_BYTES)
#define NEGINF_F (__int_as_float(0xff800000))

__global__ __launch_bounds__(256, 1) void flash_hmma_kernel(
    const __nv_bfloat16* __restrict__ qhg, const __nv_bfloat16* __restrict__ qlg,
    const __nv_bfloat16* __restrict__ khg, const __nv_bfloat16* __restrict__ klg,
    const __nv_bfloat16* __restrict__ vhg, const __nv_bfloat16* __restrict__ vlg,
    uint32_t* __restrict__ outH, uint32_t* __restrict__ outL) {
    int qt = gridDim.x - 1 - blockIdx.x;
    int h = blockIdx.y;
    int b = blockIdx.z;
    int kvh = h >> 2;
    int bh = b * NH_ + h;
    int bk = b * NKV_ + kvh;

    extern __shared__ __align__(16) char sm[];
    uint32_t sbase = smem_u32(sm);

    int tid = threadIdx.x;
    int w = tid >> 5, lane = tid & 31;
    int g = lane >> 2, t = lane & 3;
    int r8 = lane & 7, sel = lane >> 3;

    uint32_t qoff = (uint32_t)((w * 16 + (sel & 1) * 8 + r8) * 272 +
                               (sel >> 1) * 16);
    uint32_t koff = (uint32_t)((((lane >> 4) & 1) * 8 + r8) * 272 +
                               ((lane >> 3) & 1) * 16);
    uint32_t voff = (uint32_t)((((lane >> 4) & 1) * 8 + r8) * 144 +
                               ((lane >> 3) & 1) * 16);

    {
        const __nv_bfloat16* qh_g = qhg + ((size_t)bh * S_ + qt * 128) * 128;
        const __nv_bfloat16* ql_g = qlg + ((size_t)bh * S_ + qt * 128) * 128;
#pragma unroll
        for (int i = 0; i < 8; i++) {
            int c = tid + i * 256;
            int row = c >> 4, c16 = c & 15;
            cp16(sbase + FL_QH + row * 272 + c16 * 16, qh_g + row * 128 + c16 * 8);
            cp16(sbase + FL_QL + row * 272 + c16 * 16, ql_g + row * 128 + c16 * 8);
        }
        asm volatile("cp.async.commit_group;" ::: "memory");
    }

    const __nv_bfloat16* kh_b = khg + (size_t)bk * S_ * 128;
    const __nv_bfloat16* kl_b = klg + (size_t)bk * S_ * 128;
    const __nv_bfloat16* vh_b = vhg + (size_t)bk * 128 * S_;
    const __nv_bfloat16* vl_b = vlg + (size_t)bk * 128 * S_;

    auto load_kv = [&](int jt, int stg) {
        uint32_t sb = sbase + FL_STG + stg * FL_STG_BYTES;
#pragma unroll
        for (int i = 0; i < 4; i++) {
            int c = tid + i * 256;
            int row = c >> 4, c16 = c & 15;
            size_t go = ((size_t)(jt * 64 + row)) * 128 + c16 * 8;
            cp16(sb + row * 272 + c16 * 16, kh_b + go);
            cp16(sb + FL_KL + row * 272 + c16 * 16, kl_b + go);
        }
#pragma unroll
        for (int i = 0; i < 4; i++) {
            int c = tid + i * 256;
            int row = c >> 3, c8 = c & 7;
            size_t go = (size_t)row * S_ + jt * 64 + c8 * 8;
            cp16(sb + FL_VH + row * 144 + c8 * 16, vh_b + go);
            cp16(sb + FL_VL + row * 144 + c8 * 16, vl_b + go);
        }
        asm volatile("cp.async.commit_group;" ::: "memory");
    };

    int njt = 2 * qt + 2;
    load_kv(0, 0);
    load_kv(1, 1);
    asm volatile("cp.async.wait_group 2;" ::: "memory");
    __syncthreads();

    uint32_t qfh[8][4], qfl[8][4];
#pragma unroll
    for (int kk = 0; kk < 8; kk++) {
        ldsm4(qfh[kk], sbase + FL_QH + qoff + kk * 32);
        ldsm4(qfl[kk], sbase + FL_QL + qoff + kk * 32);
    }

    float o_[16][4];
#pragma unroll
    for (int n = 0; n < 16; n++)
#pragma unroll
        for (int j = 0; j < 4; j++) o_[n][j] = 0.0f;
    float m0 = NEGINF_F, m1 = NEGINF_F, l0 = 0.0f, l1 = 0.0f;

    for (int jt = 0; jt < njt; jt++) {
        if (jt < njt - 1)
            asm volatile("cp.async.wait_group 1;" ::: "memory");
        else
            asm volatile("cp.async.wait_group 0;" ::: "memory");
        __syncthreads();

        uint32_t kst = sbase + FL_STG + (jt & 1) * FL_STG_BYTES;

        float s[8][4];
#pragma unroll
        for (int j = 0; j < 8; j++)
#pragma unroll
            for (int x = 0; x < 4; x++) s[j][x] = 0.0f;

        for (int kk = 0; kk < 8; kk++) {
#pragma unroll
            for (int jp = 0; jp < 4; jp++) {
                uint32_t kb[4], lb[4];
                uint32_t ko = koff + jp * (16 * 272) + kk * 32;
                ldsm4(kb, kst + ko);
                ldsm4(lb, kst + FL_KL + ko);
                mma_bf16(s[2 * jp], qfh[kk][0], qfh[kk][1], qfh[kk][2],
                         qfh[kk][3], kb[0], kb[1]);
                mma_bf16(s[2 * jp + 1], qfh[kk][0], qfh[kk][1], qfh[kk][2],
                         qfh[kk][3], kb[2], kb[3]);
                mma_bf16(s[2 * jp], qfh[kk][0], qfh[kk][1], qfh[kk][2],
                         qfh[kk][3], lb[0], lb[1]);
                mma_bf16(s[2 * jp + 1], qfh[kk][0], qfh[kk][1], qfh[kk][2],
                         qfh[kk][3], lb[2], lb[3]);
                mma_bf16(s[2 * jp], qfl[kk][0], qfl[kk][1], qfl[kk][2],
                         qfl[kk][3], kb[0], kb[1]);
                mma_bf16(s[2 * jp + 1], qfl[kk][0], qfl[kk][1], qfl[kk][2],
                         qfl[kk][3], kb[2], kb[3]);
            }
        }

        if (jt * 64 + 63 > qt * 128 + w * 16) {
            int row0 = qt * 128 + w * 16 + g;
            int row1 = row0 + 8;
#pragma unroll
            for (int j = 0; j < 8; j++) {
                int col = jt * 64 + 8 * j + 2 * t;
                if (col > row0) s[j][0] = NEGINF_F;
                if (col + 1 > row0) s[j][1] = NEGINF_F;
                if (col > row1) s[j][2] = NEGINF_F;
                if (col + 1 > row1) s[j][3] = NEGINF_F;
            }
        }

        float mx0 = NEGINF_F, mx1 = NEGINF_F;
#pragma unroll
        for (int j = 0; j < 8; j++) {
            mx0 = fmaxf(mx0, fmaxf(s[j][0], s[j][1]));
            mx1 = fmaxf(mx1, fmaxf(s[j][2], s[j][3]));
        }
        mx0 = fmaxf(mx0, __shfl_xor_sync(0xffffffff, mx0, 1));
        mx0 = fmaxf(mx0, __shfl_xor_sync(0xffffffff, mx0, 2));
        mx1 = fmaxf(mx1, __shfl_xor_sync(0xffffffff, mx1, 1));
        mx1 = fmaxf(mx1, __shfl_xor_sync(0xffffffff, mx1, 2));
        float mn0 = fmaxf(m0, mx0), mn1 = fmaxf(m1, mx1);
        float a0 = ex2(m0 - mn0), a1 = ex2(m1 - mn1);
        m0 = mn0;
        m1 = mn1;
        float sum0 = 0.0f, sum1 = 0.0f;
#pragma unroll
        for (int j = 0; j < 8; j++) {
            s[j][0] = ex2(s[j][0] - mn0);
            s[j][1] = ex2(s[j][1] - mn0);
            s[j][2] = ex2(s[j][2] - mn1);
            s[j][3] = ex2(s[j][3] - mn1);
            sum0 += s[j][0] + s[j][1];
            sum1 += s[j][2] + s[j][3];
        }
        sum0 += __shfl_xor_sync(0xffffffff, sum0, 1);
        sum0 += __shfl_xor_sync(0xffffffff, sum0, 2);
        sum1 += __shfl_xor_sync(0xffffffff, sum1, 1);
        sum1 += __shfl_xor_sync(0xffffffff, sum1, 2);
        l0 = l0 * a0 + sum0;
        l1 = l1 * a1 + sum1;
#pragma unroll
        for (int n = 0; n < 16; n++) {
            o_[n][0] *= a0;
            o_[n][1] *= a0;
            o_[n][2] *= a1;
            o_[n][3] *= a1;
        }

#pragma unroll
        for (int kk = 0; kk < 4; kk++) {
            uint32_t pa0, pa1, pa2, pa3, la0, la1, la2, la3;
            split_pack(s[2 * kk][0], s[2 * kk][1], pa0, la0);
            split_pack(s[2 * kk][2], s[2 * kk][3], pa1, la1);
            split_pack(s[2 * kk + 1][0], s[2 * kk + 1][1], pa2, la2);
            split_pack(s[2 * kk + 1][2], s[2 * kk + 1][3], pa3, la3);
#pragma unroll
            for (int np = 0; np < 8; np++) {
                uint32_t vb[4], wb[4];
                uint32_t vo = voff + np * (16 * 144) + kk * 32;
                ldsm4(vb, kst + FL_VH + vo);
                ldsm4(wb, kst + FL_VL + vo);
                mma_bf16(o_[2 * np], pa0, pa1, pa2, pa3, vb[0], vb[1]);
                mma_bf16(o_[2 * np + 1], pa0, pa1, pa2, pa3, vb[2], vb[3]);
                mma_bf16(o_[2 * np], pa0, pa1, pa2, pa3, wb[0], wb[1]);
                mma_bf16(o_[2 * np + 1], pa0, pa1, pa2, pa3, wb[2], wb[3]);
                mma_bf16(o_[2 * np], la0, la1, la2, la3, vb[0], vb[1]);
                mma_bf16(o_[2 * np + 1], la0, la1, la2, la3, vb[2], vb[3]);
            }
        }

        __syncthreads();
        if (jt + 2 < njt) load_kv(jt + 2, jt & 1);
    }

    float inv0 = 1.0f / l0, inv1 = 1.0f / l1;
    int row0 = qt * 128 + w * 16 + g;
    int row1 = row0 + 8;
#pragma unroll
    for (int n = 0; n < 16; n++) {
        int col = h * 128 + 8 * n + 2 * t;
        uint32_t hi0, lo0, hi1, lo1;
        split_pack(o_[n][0] * inv0, o_[n][1] * inv0, hi0, lo0);
        split_pack(o_[n][2] * inv1, o_[n][3] * inv1, hi1, lo1);
        size_t w0 = ((size_t)(b * S_ + row0) * 2048 + col) >> 1;
        size_t w1 = ((size_t)(b * S_ + row1) * 2048 + col) >> 1;
        outH[w0] = hi0;
        outL[w0] = lo0;
        outH[w1] = hi1;
        outL[w1] = lo1;
    }
}

// ---------------- launch ----------------------------------------------------
extern "C" void kernel_launch(void* const* d_in, const int* in_sizes, int n_in,
                              void* d_out, int out_size) {
    const float* hs  = (const float*)d_in[0];
    const float* q_w = (const float*)d_in[1];
    const float* q_b = (const float*)d_in[2];
    const float* k_w = (const float*)d_in[3];
    const float* k_b = (const float*)d_in[4];
    const float* v_w = (const float*)d_in[5];
    const float* v_b = (const float*)d_in[6];
    const float* o_w = (const float*)d_in[7];
    float* out = (float*)d_out;

    float *vp, *cp, *sp;
    cudaGetSymbolAddress((void**)&vp, g_v);
    cudaGetSymbolAddress((void**)&cp, g_cos);
    cudaGetSymbolAddress((void**)&sp, g_sin);

    __nv_bfloat16 *hsh, *hsl, *ath, *atl, *w3h, *w3l, *owh, *owl;
    cudaGetSymbolAddress((void**)&hsh, g_hs_h);
    cudaGetSymbolAddress((void**)&hsl, g_hs_l);
    cudaGetSymbolAddress((void**)&ath, g_at_h);
    cudaGetSymbolAddress((void**)&atl, g_at_l);
    cudaGetSymbolAddress((void**)&w3h, g_w3_h);
    cudaGetSymbolAddress((void**)&w3l, g_w3_l);
    cudaGetSymbolAddress((void**)&owh, g_ow_h);
    cudaGetSymbolAddress((void**)&owl, g_ow_l);

    __nv_bfloat16 *qh, *ql, *kh, *kl, *vh, *vl;
    cudaGetSymbolAddress((void**)&qh, g_qh);
    cudaGetSymbolAddress((void**)&ql, g_ql);
    cudaGetSymbolAddress((void**)&kh, g_kh);
    cudaGetSymbolAddress((void**)&kl, g_kl);
    cudaGetSymbolAddress((void**)&vh, g_vh);
    cudaGetSymbolAddress((void**)&vl, g_vl);

    cudaFuncSetAttribute(hgemm_kernel<0>,
                         cudaFuncAttributeMaxDynamicSharedMemorySize, HG_SMEM);
    cudaFuncSetAttribute(hgemm_kernel<3>,
                         cudaFuncAttributeMaxDynamicSharedMemorySize, HG_SMEM);
    cudaFuncSetAttribute(flash_hmma_kernel,
                         cudaFuncAttributeMaxDynamicSharedMemorySize, FL_SMEM);

    dim3 tb(32, 8);

    // #1 activation split + RoPE table
    int n4_hs = (ROWS_ * HID_) / 4;
    split_hs_rope_kernel<<<(n4_hs + 255) / 256, 256>>>(hs, hsh, hsl, n4_hs, cp, sp);

    // #2 fused QKV weight transpose -> W3
    transpose_w3_kernel<<<dim3(96, 64), tb>>>(q_w, k_w, v_w, w3h, w3l);

    // #3 fused QKV projection
    dim3 g3(3072 / 128, ROWS_ / 64);   // (24, 64) = 1536 CTAs
    hgemm_kernel<3><<<g3, 256, HG_SMEM>>>(hsh, hsl, w3h, w3l,
                                          q_b, k_b, v_b, vp,
                                          (uint32_t*)qh, (uint32_t*)ql,
                                          (uint32_t*)kh, (uint32_t*)kl,
                                          cp, sp, ROWS_, 3072, HID_);

    // #4 O weight transpose
    transpose_split_kernel<<<dim3(2048 / 32, 2048 / 32), tb>>>(o_w, owh, owl,
                                                               2048, 2048);

    // #5 V transpose+split
    dim3 tv(32, 8);
    split_vt_kernel<<<dim3(S_ / 32, HD_ / 32, B_ * NKV_), tv>>>(vp, vh, vl);

    // #6 Flash attention
    dim3 gf(S_ / 128, NH_, B_);
    flash_hmma_kernel<<<gf, 256, FL_SMEM>>>(qh, ql, kh, kl, vh, vl,
                                            (uint32_t*)ath, (uint32_t*)atl);

    // #7 Output projection (fp32 out)
    dim3 go(2048 / 128, ROWS_ / 64);   // (16, 64)
    hgemm_kernel<0><<<go, 256, HG_SMEM>>>(ath, atl, owh, owl,
                                          nullptr, nullptr, nullptr, out,
                                          nullptr, nullptr, nullptr, nullptr,
                                          nullptr, nullptr, ROWS_, HID_,
                                          NH_ * HD_);
}

// round 16
// speedup vs baseline: 1.1151x; 1.1151x over previous
#include <cuda_runtime.h>
#include <cuda_bf16.h>
#include <math.h>
#include <math_constants.h>
#include <cstdint>

// Problem constants
#define B_   2
#define S_   2048
#define HID_ 2048
#define NH_  16
#define NKV_ 4
#define HD_  128
#define ROWS_ (B_ * S_)          // 4096

// Q pre-scale: 1/sqrt(128) * log2(e)
#define QSC ((float)(0.08838834764831845 * 1.4426950408889634))

// ---------------- scratch (device globals; no allocation allowed) ----------
__device__ float g_v[ROWS_ * NKV_ * HD_];    // fp32 V (pre-transpose)
__device__ float g_cos[S_ * 64];
__device__ float g_sin[S_ * 64];

// bf16 split operands
__device__ __nv_bfloat16 g_hs_h[ROWS_ * HID_];
__device__ __nv_bfloat16 g_hs_l[ROWS_ * HID_];
__device__ __nv_bfloat16 g_at_h[ROWS_ * HID_];
__device__ __nv_bfloat16 g_at_l[ROWS_ * HID_];
__device__ __nv_bfloat16 g_w3_h[3072 * 2048];  // [Q|K|V] weights, [N,K]
__device__ __nv_bfloat16 g_w3_l[3072 * 2048];
__device__ __nv_bfloat16 g_ow_h[2048 * 2048];
__device__ __nv_bfloat16 g_ow_l[2048 * 2048];

__device__ __nv_bfloat16 g_qh[B_ * NH_ * S_ * HD_];   // [b][h][s][d]
__device__ __nv_bfloat16 g_ql[B_ * NH_ * S_ * HD_];
__device__ __nv_bfloat16 g_kh[B_ * NKV_ * S_ * HD_];  // [b][kvh][s][d]
__device__ __nv_bfloat16 g_kl[B_ * NKV_ * S_ * HD_];
__device__ __nv_bfloat16 g_vh[B_ * NKV_ * HD_ * S_];  // [b][kvh][d][s]
__device__ __nv_bfloat16 g_vl[B_ * NKV_ * HD_ * S_];

// ====================== helpers =============================================
__device__ __forceinline__ uint32_t smem_u32(const void* p) {
    uint32_t r;
    asm("{ .reg .u64 t; cvta.to.shared.u64 t, %1; cvt.u32.u64 %0, t; }"
        : "=r"(r) : "l"(p));
    return r;
}

__device__ __forceinline__ void cp16(uint32_t dst, const void* src) {
    asm volatile("cp.async.cg.shared.global [%0], [%1], 16;"
                 :: "r"(dst), "l"(src) : "memory");
}

__device__ __forceinline__ float ex2(float x) {
    float r;
    asm("ex2.approx.f32 %0, %1;" : "=f"(r) : "f"(x));
    return r;
}

__device__ __forceinline__ void mma_bf16(float c[4], uint32_t a0, uint32_t a1,
                                         uint32_t a2, uint32_t a3,
                                         uint32_t b0, uint32_t b1) {
    asm volatile(
        "mma.sync.aligned.m16n8k16.row.col.f32.bf16.bf16.f32 "
        "{%0,%1,%2,%3}, {%4,%5,%6,%7}, {%8,%9}, {%0,%1,%2,%3};"
        : "+f"(c[0]), "+f"(c[1]), "+f"(c[2]), "+f"(c[3])
        : "r"(a0), "r"(a1), "r"(a2), "r"(a3), "r"(b0), "r"(b1));
}

__device__ __forceinline__ void ldsm4(uint32_t a[4], uint32_t addr) {
    asm volatile("ldmatrix.sync.aligned.m8n8.x4.shared.b16 {%0,%1,%2,%3}, [%4];"
                 : "=r"(a[0]), "=r"(a[1]), "=r"(a[2]), "=r"(a[3]) : "r"(addr));
}

__device__ __forceinline__ void split_pack(float x0, float x1,
                                           uint32_t& hi, uint32_t& lo) {
    uint32_t h;
    asm("cvt.rn.bf16x2.f32 %0, %1, %2;" : "=r"(h) : "f"(x1), "f"(x0));
    float h0 = __uint_as_float(h << 16);
    float h1 = __uint_as_float(h & 0xFFFF0000u);
    float r0 = x0 - h0, r1 = x1 - h1;
    uint32_t l;
    asm("cvt.rn.bf16x2.f32 %0, %1, %2;" : "=r"(l) : "f"(r1), "f"(r0));
    hi = h;
    lo = l;
}

// ================= HMMA split-bf16 GEMM (fused epilogues) ===================
// C[M,N] = A[M,K] @ Bt[N,K]^T. 3-stage cp.async pipeline, pitch 80B, 2 CTAs/SM.
// BM=64 BN=128 BK=32, 256 threads (8 warps 2x4), warp tile 32x32.
// Prefetch AFTER compute burst (R13-proven schedule).
// MODE 0: fp32 out to C. MODE 3: fused QKV epilogue by n0.
#define HG_P    80
#define HG_SA_L 5120
#define HG_SB_H 10240
#define HG_SB_L 20480
#define HG_STAGE 30720
#define HG_SMEM (3 * HG_STAGE)   // 92160 per CTA -> 2 CTAs/SM

template <int MODE>
__global__ __launch_bounds__(256, 2) void hgemm_kernel(
    const __nv_bfloat16* __restrict__ Ah, const __nv_bfloat16* __restrict__ Al,
    const __nv_bfloat16* __restrict__ Bh, const __nv_bfloat16* __restrict__ Bl,
    const float* __restrict__ qb, const float* __restrict__ kb,
    const float* __restrict__ vb, float* __restrict__ C,
    uint32_t* __restrict__ OH, uint32_t* __restrict__ OL,
    uint32_t* __restrict__ OH2, uint32_t* __restrict__ OL2,
    const float* __restrict__ cs, const float* __restrict__ sn,
    int M, int N, int K) {
    extern __shared__ __align__(16) char smc[];
    uint32_t sb = smem_u32(smc);
    int tid = threadIdx.x, wid = tid >> 5, lane = tid & 31;
    int warp_m = wid >> 2, warp_n = wid & 3;
    int m0 = blockIdx.y * 64, n0 = blockIdx.x * 128;
    int g = lane >> 2, t = lane & 3;

    int r8 = lane & 7, sel = lane >> 3;
    uint32_t aoff = (uint32_t)((warp_m * 32 + (sel & 1) * 8 + r8) * HG_P +
                               (sel >> 1) * 16);
    uint32_t boff = (uint32_t)((warp_n * 32 + ((lane >> 4) & 1) * 8 + r8) * HG_P +
                               ((lane >> 3) & 1) * 16);

    auto load_stage = [&](int k0, int stg) {
        uint32_t st = sb + stg * HG_STAGE;
        {
            int row = tid >> 2, seg = tid & 3;
            uint32_t so = row * HG_P + seg * 16;
            size_t ga = (size_t)(m0 + row) * K + k0 + seg * 8;
            cp16(st + so, Ah + ga);
            cp16(st + HG_SA_L + so, Al + ga);
        }
#pragma unroll
        for (int i = 0; i < 2; i++) {
            int idx = tid + i * 256;
            int row = idx >> 2, seg = idx & 3;
            uint32_t so = row * HG_P + seg * 16;
            size_t gb = (size_t)(n0 + row) * K + k0 + seg * 8;
            cp16(st + HG_SB_H + so, Bh + gb);
            cp16(st + HG_SB_L + so, Bl + gb);
        }
        asm volatile("cp.async.commit_group;" ::: "memory");
    };

    float acc[2][4][4];
#pragma unroll
    for (int i = 0; i < 2; i++)
#pragma unroll
        for (int j = 0; j < 4; j++)
#pragma unroll
            for (int x = 0; x < 4; x++) acc[i][j][x] = 0.0f;

    const int niter = K / 32;
    load_stage(0, 0);
    load_stage(32, 1);

    for (int it = 0; it < niter; it++) {
        if (it < niter - 1)
            asm volatile("cp.async.wait_group 1;" ::: "memory");
        else
            asm volatile("cp.async.wait_group 0;" ::: "memory");
        __syncthreads();
        int s3 = it % 3;
        uint32_t st = sb + s3 * HG_STAGE;

#pragma unroll
        for (int kc = 0; kc < 2; kc++) {
            uint32_t ah[2][4], al[2][4];
#pragma unroll
            for (int fm = 0; fm < 2; fm++) {
                ldsm4(ah[fm], st + aoff + fm * (16 * HG_P) + kc * 32);
                ldsm4(al[fm], st + HG_SA_L + aoff + fm * (16 * HG_P) + kc * 32);
            }
            uint32_t bh4[2][4], bl4[2][4];
#pragma unroll
            for (int fnp = 0; fnp < 2; fnp++) {
                uint32_t bo = boff + fnp * (16 * HG_P) + kc * 32;
                ldsm4(bh4[fnp], st + HG_SB_H + bo);
                ldsm4(bl4[fnp], st + HG_SB_L + bo);
            }
#pragma unroll
            for (int fm = 0; fm < 2; fm++)
#pragma unroll
                for (int fnp = 0; fnp < 2; fnp++) {
                    mma_bf16(acc[fm][2 * fnp], ah[fm][0], ah[fm][1], ah[fm][2],
                             ah[fm][3], bh4[fnp][0], bh4[fnp][1]);
                    mma_bf16(acc[fm][2 * fnp + 1], ah[fm][0], ah[fm][1],
                             ah[fm][2], ah[fm][3], bh4[fnp][2], bh4[fnp][3]);
                }
#pragma unroll
            for (int fm = 0; fm < 2; fm++)
#pragma unroll
                for (int fnp = 0; fnp < 2; fnp++) {
                    mma_bf16(acc[fm][2 * fnp], ah[fm][0], ah[fm][1], ah[fm][2],
                             ah[fm][3], bl4[fnp][0], bl4[fnp][1]);
                    mma_bf16(acc[fm][2 * fnp + 1], ah[fm][0], ah[fm][1],
                             ah[fm][2], ah[fm][3], bl4[fnp][2], bl4[fnp][3]);
                }
#pragma unroll
            for (int fm = 0; fm < 2; fm++)
#pragma unroll
                for (int fnp = 0; fnp < 2; fnp++) {
                    mma_bf16(acc[fm][2 * fnp], al[fm][0], al[fm][1], al[fm][2],
                             al[fm][3], bh4[fnp][0], bh4[fnp][1]);
                    mma_bf16(acc[fm][2 * fnp + 1], al[fm][0], al[fm][1],
                             al[fm][2], al[fm][3], bh4[fnp][2], bh4[fnp][3]);
                }
        }
        if (it + 2 < niter) load_stage((it + 2) * 32, (it + 2) % 3);
    }

    // epilogue
#pragma unroll
    for (int fm = 0; fm < 2; fm++) {
        int row0 = m0 + warp_m * 32 + fm * 16 + g;
#pragma unroll
        for (int fn = 0; fn < 4; fn++) {
            int col = n0 + warp_n * 32 + fn * 8 + 2 * t;
            if (MODE == 0) {
                float2 v0, v1;
                v0.x = acc[fm][fn][0];
                v0.y = acc[fm][fn][1];
                v1.x = acc[fm][fn][2];
                v1.y = acc[fm][fn][3];
                *(float2*)(C + (size_t)row0 * N + col) = v0;
                *(float2*)(C + (size_t)(row0 + 8) * N + col) = v1;
            } else if (n0 < 2048) {
                float2 bb = *(const float2*)(qb + col);
                float vx[2] = {acc[fm][fn][0] + bb.x, acc[fm][fn][2] + bb.x};
                float vy[2] = {acc[fm][fn][1] + bb.y, acc[fm][fn][3] + bb.y};
                int hh = col >> 7;
                int p = (col & 127) >> 1;
#pragma unroll
                for (int rr = 0; rr < 2; rr++) {
                    int row = row0 + rr * 8;
                    int s = row & (S_ - 1);
                    int bb_ = row >> 11;
                    float cv = cs[s * 64 + p];
                    float sv = sn[s * 64 + p];
                    float o1 = (vx[rr] * cv - vy[rr] * sv) * QSC;
                    float o2 = (vx[rr] * sv + vy[rr] * cv) * QSC;
                    uint32_t hi, lo;
                    split_pack(o1, o2, hi, lo);
                    size_t wi = (((size_t)bb_ * NH_ + hh) * S_ + s) * 64 + p;
                    OH[wi] = hi;
                    OL[wi] = lo;
                }
            } else if (n0 < 2560) {
                int c2 = col - 2048;
                float2 bb = *(const float2*)(kb + c2);
                float vx[2] = {acc[fm][fn][0] + bb.x, acc[fm][fn][2] + bb.x};
                float vy[2] = {acc[fm][fn][1] + bb.y, acc[fm][fn][3] + bb.y};
                int hh = c2 >> 7;
                int p = (c2 & 127) >> 1;
#pragma unroll
                for (int rr = 0; rr < 2; rr++) {
                    int row = row0 + rr * 8;
                    int s = row & (S_ - 1);
                    int bb_ = row >> 11;
                    float cv = cs[s * 64 + p];
                    float sv = sn[s * 64 + p];
                    float o1 = vx[rr] * cv - vy[rr] * sv;
                    float o2 = vx[rr] * sv + vy[rr] * cv;
                    uint32_t hi, lo;
                    split_pack(o1, o2, hi, lo);
                    size_t wi = (((size_t)bb_ * NKV_ + hh) * S_ + s) * 64 + p;
                    OH2[wi] = hi;
                    OL2[wi] = lo;
                }
            } else {
                int c2 = col - 2560;
                float2 bb = *(const float2*)(vb + c2);
                float2 v0, v1;
                v0.x = acc[fm][fn][0] + bb.x;
                v0.y = acc[fm][fn][1] + bb.y;
                v1.x = acc[fm][fn][2] + bb.x;
                v1.y = acc[fm][fn][3] + bb.y;
                *(float2*)(C + (size_t)row0 * 512 + c2) = v0;
                *(float2*)(C + (size_t)(row0 + 8) * 512 + c2) = v1;
            }
        }
    }
}

// ---------------- conversion kernels ----------------------------------------
__global__ void split_hs_rope_kernel(const float* __restrict__ x,
                                     __nv_bfloat16* __restrict__ h,
                                     __nv_bfloat16* __restrict__ l, int n4,
                                     float* __restrict__ cs,
                                     float* __restrict__ sn) {
    int i = blockIdx.x * blockDim.x + threadIdx.x;
    if (blockIdx.x < 512) {
        int idx = i;
        int s = idx >> 6;
        int p = idx & 63;
        double freq = exp(-((double)(2 * p) / (double)HD_) * log(10000.0));
        double ang = (double)s * freq;
        double sv, cv;
        sincos(ang, &sv, &cv);
        cs[idx] = (float)cv;
        sn[idx] = (float)sv;
    }
    if (i >= n4) return;
    float4 v = ((const float4*)x)[i];
    uint32_t h0, l0, h1, l1;
    split_pack(v.x, v.y, h0, l0);
    split_pack(v.z, v.w, h1, l1);
    ((uint32_t*)h)[i * 2 + 0] = h0;
    ((uint32_t*)h)[i * 2 + 1] = h1;
    ((uint32_t*)l)[i * 2 + 0] = l0;
    ((uint32_t*)l)[i * 2 + 1] = l1;
}

// Fused weight transpose for ALL weights:
// rows [0,3072)  -> W3 (Q|K|V) [3072][2048]
// rows [3072,5120) -> OW [2048][2048]
__global__ void transpose_all_kernel(const float* __restrict__ qw,
                                     const float* __restrict__ kw,
                                     const float* __restrict__ vw,
                                     const float* __restrict__ ow,
                                     __nv_bfloat16* __restrict__ W3h,
                                     __nv_bfloat16* __restrict__ W3l,
                                     __nv_bfloat16* __restrict__ OWh,
                                     __nv_bfloat16* __restrict__ OWl) {
    __shared__ float tshm[32][33];
    int colg = blockIdx.x * 32;        // [0, 5120)
    int k0 = blockIdx.y * 32;
    const float* W;
    __nv_bfloat16 *Th, *Tl;
    int N, n0, obase;
    if (colg < 2048) {
        W = qw; N = 2048; n0 = colg; obase = colg; Th = W3h; Tl = W3l;
    } else if (colg < 2560) {
        W = kw; N = 512; n0 = colg - 2048; obase = colg; Th = W3h; Tl = W3l;
    } else if (colg < 3072) {
        W = vw; N = 512; n0 = colg - 2560; obase = colg; Th = W3h; Tl = W3l;
    } else {
        W = ow; N = 2048; n0 = colg - 3072; obase = colg - 3072; Th = OWh; Tl = OWl;
    }
    int tx = threadIdx.x, ty = threadIdx.y;  // (32,8)
#pragma unroll
    for (int i = 0; i < 32; i += 8)
        tshm[ty + i][tx] = W[(size_t)(k0 + ty + i) * N + n0 + tx];
    __syncthreads();
#pragma unroll
    for (int i = 0; i < 32; i += 8) {
        int n = obase + ty + i, k = k0 + tx;
        float v = tshm[tx][ty + i];
        __nv_bfloat16 hb = __float2bfloat16(v);
        Th[(size_t)n * 2048 + k] = hb;
        Tl[(size_t)n * 2048 + k] = __float2bfloat16(v - __bfloat162float(hb));
    }
}

// V: fp32 -> bf16 hi/lo TRANSPOSED [b][kvh][d][s]
__global__ void split_vt_kernel(const float* __restrict__ v,
                                __nv_bfloat16* __restrict__ vh,
                                __nv_bfloat16* __restrict__ vl) {
    __shared__ float tshm[32][33];
    int bk = blockIdx.z;
    int b = bk >> 2, kvh = bk & 3;
    int s0 = blockIdx.x * 32, d0 = blockIdx.y * 32;
    int tx = threadIdx.x, ty = threadIdx.y;
#pragma unroll
    for (int i = 0; i < 32; i += 8)
        tshm[ty + i][tx] = v[((size_t)(b * S_ + s0 + ty + i)) * 512 + kvh * 128 + d0 + tx];
    __syncthreads();
#pragma unroll
    for (int i = 0; i < 32; i += 8) {
        float x = tshm[tx][ty + i];
        __nv_bfloat16 hb = __float2bfloat16(x);
        size_t o = ((size_t)bk * 128 + d0 + ty + i) * (size_t)S_ + s0 + tx;
        vh[o] = hb;
        vl[o] = __float2bfloat16(x - __bfloat162float(hb));
    }
}

// ---------------- Flash attention (HMMA, bf16 3-term split, ldmatrix) -------
#define FL_QL 0
#define FL_QH 34816
#define FL_STG 69632
#define FL_STG_BYTES 71680
#define FL_KL 17408
#define FL_VH 34816
#define FL_VL 53248
#define FL_SMEM (FL_STG + 2 * FL_STG_BYTES)
#define NEGINF_F (__int_as_float(0xff800000))

__global__ __launch_bounds__(256, 1) void flash_hmma_kernel(
    const __nv_bfloat16* __restrict__ qhg, const __nv_bfloat16* __restrict__ qlg,
    const __nv_bfloat16* __restrict__ khg, const __nv_bfloat16* __restrict__ klg,
    const __nv_bfloat16* __restrict__ vhg, const __nv_bfloat16* __restrict__ vlg,
    uint32_t* __restrict__ outH, uint32_t* __restrict__ outL) {
    int qt = gridDim.x - 1 - blockIdx.x;
    int h = blockIdx.y;
    int b = blockIdx.z;
    int kvh = h >> 2;
    int bh = b * NH_ + h;
    int bk = b * NKV_ + kvh;

    extern __shared__ __align__(16) char sm[];
    uint32_t sbase = smem_u32(sm);

    int tid = threadIdx.x;
    int w = tid >> 5, lane = tid & 31;
    int g = lane >> 2, t = lane & 3;
    int r8 = lane & 7, sel = lane >> 3;

    uint32_t qoff = (uint32_t)((w * 16 + (sel & 1) * 8 + r8) * 272 +
                               (sel >> 1) * 16);
    uint32_t koff = (uint32_t)((((lane >> 4) & 1) * 8 + r8) * 272 +
                               ((lane >> 3) & 1) * 16);
    uint32_t voff = (uint32_t)((((lane >> 4) & 1) * 8 + r8) * 144 +
                               ((lane >> 3) & 1) * 16);

    {
        const __nv_bfloat16* qh_g = qhg + ((size_t)bh * S_ + qt * 128) * 128;
        const __nv_bfloat16* ql_g = qlg + ((size_t)bh * S_ + qt * 128) * 128;
#pragma unroll
        for (int i = 0; i < 8; i++) {
            int c = tid + i * 256;
            int row = c >> 4, c16 = c & 15;
            cp16(sbase + FL_QH + row * 272 + c16 * 16, qh_g + row * 128 + c16 * 8);
            cp16(sbase + FL_QL + row * 272 + c16 * 16, ql_g + row * 128 + c16 * 8);
        }
        asm volatile("cp.async.commit_group;" ::: "memory");
    }

    const __nv_bfloat16* kh_b = khg + (size_t)bk * S_ * 128;
    const __nv_bfloat16* kl_b = klg + (size_t)bk * S_ * 128;
    const __nv_bfloat16* vh_b = vhg + (size_t)bk * 128 * S_;
    const __nv_bfloat16* vl_b = vlg + (size_t)bk * 128 * S_;

    auto load_kv = [&](int jt, int stg) {
        uint32_t sb = sbase + FL_STG + stg * FL_STG_BYTES;
#pragma unroll
        for (int i = 0; i < 4; i++) {
            int c = tid + i * 256;
            int row = c >> 4, c16 = c & 15;
            size_t go = ((size_t)(jt * 64 + row)) * 128 + c16 * 8;
            cp16(sb + row * 272 + c16 * 16, kh_b + go);
            cp16(sb + FL_KL + row * 272 + c16 * 16, kl_b + go);
        }
#pragma unroll
        for (int i = 0; i < 4; i++) {
            int c = tid + i * 256;
            int row = c >> 3, c8 = c & 7;
            size_t go = (size_t)row * S_ + jt * 64 + c8 * 8;
            cp16(sb + FL_VH + row * 144 + c8 * 16, vh_b + go);
            cp16(sb + FL_VL + row * 144 + c8 * 16, vl_b + go);
        }
        asm volatile("cp.async.commit_group;" ::: "memory");
    };

    int njt = 2 * qt + 2;
    load_kv(0, 0);
    load_kv(1, 1);
    asm volatile("cp.async.wait_group 2;" ::: "memory");
    __syncthreads();

    uint32_t qfh[8][4], qfl[8][4];
#pragma unroll
    for (int kk = 0; kk < 8; kk++) {
        ldsm4(qfh[kk], sbase + FL_QH + qoff + kk * 32);
        ldsm4(qfl[kk], sbase + FL_QL + qoff + kk * 32);
    }

    float o_[16][4];
#pragma unroll
    for (int n = 0; n < 16; n++)
#pragma unroll
        for (int j = 0; j < 4; j++) o_[n][j] = 0.0f;
    float m0 = NEGINF_F, m1 = NEGINF_F, l0 = 0.0f, l1 = 0.0f;

    for (int jt = 0; jt < njt; jt++) {
        if (jt < njt - 1)
            asm volatile("cp.async.wait_group 1;" ::: "memory");
        else
            asm volatile("cp.async.wait_group 0;" ::: "memory");
        __syncthreads();

        uint32_t kst = sbase + FL_STG + (jt & 1) * FL_STG_BYTES;

        float s[8][4];
#pragma unroll
        for (int j = 0; j < 8; j++)
#pragma unroll
            for (int x = 0; x < 4; x++) s[j][x] = 0.0f;

        for (int kk = 0; kk < 8; kk++) {
#pragma unroll
            for (int jp = 0; jp < 4; jp++) {
                uint32_t kb[4], lb[4];
                uint32_t ko = koff + jp * (16 * 272) + kk * 32;
                ldsm4(kb, kst + ko);
                ldsm4(lb, kst + FL_KL + ko);
                mma_bf16(s[2 * jp], qfh[kk][0], qfh[kk][1], qfh[kk][2],
                         qfh[kk][3], kb[0], kb[1]);
                mma_bf16(s[2 * jp + 1], qfh[kk][0], qfh[kk][1], qfh[kk][2],
                         qfh[kk][3], kb[2], kb[3]);
                mma_bf16(s[2 * jp], qfh[kk][0], qfh[kk][1], qfh[kk][2],
                         qfh[kk][3], lb[0], lb[1]);
                mma_bf16(s[2 * jp + 1], qfh[kk][0], qfh[kk][1], qfh[kk][2],
                         qfh[kk][3], lb[2], lb[3]);
                mma_bf16(s[2 * jp], qfl[kk][0], qfl[kk][1], qfl[kk][2],
                         qfl[kk][3], kb[0], kb[1]);
                mma_bf16(s[2 * jp + 1], qfl[kk][0], qfl[kk][1], qfl[kk][2],
                         qfl[kk][3], kb[2], kb[3]);
            }
        }

        if (jt * 64 + 63 > qt * 128 + w * 16) {
            int row0 = qt * 128 + w * 16 + g;
            int row1 = row0 + 8;
#pragma unroll
            for (int j = 0; j < 8; j++) {
                int col = jt * 64 + 8 * j + 2 * t;
                if (col > row0) s[j][0] = NEGINF_F;
                if (col + 1 > row0) s[j][1] = NEGINF_F;
                if (col > row1) s[j][2] = NEGINF_F;
                if (col + 1 > row1) s[j][3] = NEGINF_F;
            }
        }

        float mx0 = NEGINF_F, mx1 = NEGINF_F;
#pragma unroll
        for (int j = 0; j < 8; j++) {
            mx0 = fmaxf(mx0, fmaxf(s[j][0], s[j][1]));
            mx1 = fmaxf(mx1, fmaxf(s[j][2], s[j][3]));
        }
        mx0 = fmaxf(mx0, __shfl_xor_sync(0xffffffff, mx0, 1));
        mx0 = fmaxf(mx0, __shfl_xor_sync(0xffffffff, mx0, 2));
        mx1 = fmaxf(mx1, __shfl_xor_sync(0xffffffff, mx1, 1));
        mx1 = fmaxf(mx1, __shfl_xor_sync(0xffffffff, mx1, 2));
        float mn0 = fmaxf(m0, mx0), mn1 = fmaxf(m1, mx1);
        float a0 = ex2(m0 - mn0), a1 = ex2(m1 - mn1);
        m0 = mn0;
        m1 = mn1;
        float sum0 = 0.0f, sum1 = 0.0f;
#pragma unroll
        for (int j = 0; j < 8; j++) {
            s[j][0] = ex2(s[j][0] - mn0);
            s[j][1] = ex2(s[j][1] - mn0);
            s[j][2] = ex2(s[j][2] - mn1);
            s[j][3] = ex2(s[j][3] - mn1);
            sum0 += s[j][0] + s[j][1];
            sum1 += s[j][2] + s[j][3];
        }
        sum0 += __shfl_xor_sync(0xffffffff, sum0, 1);
        sum0 += __shfl_xor_sync(0xffffffff, sum0, 2);
        sum1 += __shfl_xor_sync(0xffffffff, sum1, 1);
        sum1 += __shfl_xor_sync(0xffffffff, sum1, 2);
        l0 = l0 * a0 + sum0;
        l1 = l1 * a1 + sum1;
#pragma unroll
        for (int n = 0; n < 16; n++) {
            o_[n][0] *= a0;
            o_[n][1] *= a0;
            o_[n][2] *= a1;
            o_[n][3] *= a1;
        }

#pragma unroll
        for (int kk = 0; kk < 4; kk++) {
            uint32_t pa0, pa1, pa2, pa3, la0, la1, la2, la3;
            split_pack(s[2 * kk][0], s[2 * kk][1], pa0, la0);
            split_pack(s[2 * kk][2], s[2 * kk][3], pa1, la1);
            split_pack(s[2 * kk + 1][0], s[2 * kk + 1][1], pa2, la2);
            split_pack(s[2 * kk + 1][2], s[2 * kk + 1][3], pa3, la3);
#pragma unroll
            for (int np = 0; np < 8; np++) {
                uint32_t vb[4], wb[4];
                uint32_t vo = voff + np * (16 * 144) + kk * 32;
                ldsm4(vb, kst + FL_VH + vo);
                ldsm4(wb, kst + FL_VL + vo);
                mma_bf16(o_[2 * np], pa0, pa1, pa2, pa3, vb[0], vb[1]);
                mma_bf16(o_[2 * np + 1], pa0, pa1, pa2, pa3, vb[2], vb[3]);
                mma_bf16(o_[2 * np], pa0, pa1, pa2, pa3, wb[0], wb[1]);
                mma_bf16(o_[2 * np + 1], pa0, pa1, pa2, pa3, wb[2], wb[3]);
                mma_bf16(o_[2 * np], la0, la1, la2, la3, vb[0], vb[1]);
                mma_bf16(o_[2 * np + 1], la0, la1, la2, la3, vb[2], vb[3]);
            }
        }

        __syncthreads();
        if (jt + 2 < njt) load_kv(jt + 2, jt & 1);
    }

    float inv0 = 1.0f / l0, inv1 = 1.0f / l1;
    int row0 = qt * 128 + w * 16 + g;
    int row1 = row0 + 8;
#pragma unroll
    for (int n = 0; n < 16; n++) {
        int col = h * 128 + 8 * n + 2 * t;
        uint32_t hi0, lo0, hi1, lo1;
        split_pack(o_[n][0] * inv0, o_[n][1] * inv0, hi0, lo0);
        split_pack(o_[n][2] * inv1, o_[n][3] * inv1, hi1, lo1);
        size_t w0 = ((size_t)(b * S_ + row0) * 2048 + col) >> 1;
        size_t w1 = ((size_t)(b * S_ + row1) * 2048 + col) >> 1;
        outH[w0] = hi0;
        outL[w0] = lo0;
        outH[w1] = hi1;
        outL[w1] = lo1;
    }
}

// ---------------- launch ----------------------------------------------------
extern "C" void kernel_launch(void* const* d_in, const int* in_sizes, int n_in,
                              void* d_out, int out_size) {
    const float* hs  = (const float*)d_in[0];
    const float* q_w = (const float*)d_in[1];
    const float* q_b = (const float*)d_in[2];
    const float* k_w = (const float*)d_in[3];
    const float* k_b = (const float*)d_in[4];
    const float* v_w = (const float*)d_in[5];
    const float* v_b = (const float*)d_in[6];
    const float* o_w = (const float*)d_in[7];
    float* out = (float*)d_out;

    float *vp, *cp, *sp;
    cudaGetSymbolAddress((void**)&vp, g_v);
    cudaGetSymbolAddress((void**)&cp, g_cos);
    cudaGetSymbolAddress((void**)&sp, g_sin);

    __nv_bfloat16 *hsh, *hsl, *ath, *atl, *w3h, *w3l, *owh, *owl;
    cudaGetSymbolAddress((void**)&hsh, g_hs_h);
    cudaGetSymbolAddress((void**)&hsl, g_hs_l);
    cudaGetSymbolAddress((void**)&ath, g_at_h);
    cudaGetSymbolAddress((void**)&atl, g_at_l);
    cudaGetSymbolAddress((void**)&w3h, g_w3_h);
    cudaGetSymbolAddress((void**)&w3l, g_w3_l);
    cudaGetSymbolAddress((void**)&owh, g_ow_h);
    cudaGetSymbolAddress((void**)&owl, g_ow_l);

    __nv_bfloat16 *qh, *ql, *kh, *kl, *vh, *vl;
    cudaGetSymbolAddress((void**)&qh, g_qh);
    cudaGetSymbolAddress((void**)&ql, g_ql);
    cudaGetSymbolAddress((void**)&kh, g_kh);
    cudaGetSymbolAddress((void**)&kl, g_kl);
    cudaGetSymbolAddress((void**)&vh, g_vh);
    cudaGetSymbolAddress((void**)&vl, g_vl);

    cudaFuncSetAttribute(hgemm_kernel<0>,
                         cudaFuncAttributeMaxDynamicSharedMemorySize, HG_SMEM);
    cudaFuncSetAttribute(hgemm_kernel<3>,
                         cudaFuncAttributeMaxDynamicSharedMemorySize, HG_SMEM);
    cudaFuncSetAttribute(flash_hmma_kernel,
                         cudaFuncAttributeMaxDynamicSharedMemorySize, FL_SMEM);

    dim3 tb(32, 8);

    // #1 activation split + RoPE table
    int n4_hs = (ROWS_ * HID_) / 4;
    split_hs_rope_kernel<<<(n4_hs + 255) / 256, 256>>>(hs, hsh, hsl, n4_hs, cp, sp);

    // #2 ALL weight transposes in one launch (Q|K|V -> W3, O -> OW)
    transpose_all_kernel<<<dim3(160, 64), tb>>>(q_w, k_w, v_w, o_w,
                                                w3h, w3l, owh, owl);

    // #3 fused QKV projection
    dim3 g3(3072 / 128, ROWS_ / 64);   // (24, 64) = 1536 CTAs
    hgemm_kernel<3><<<g3, 256, HG_SMEM>>>(hsh, hsl, w3h, w3l,
                                          q_b, k_b, v_b, vp,
                                          (uint32_t*)qh, (uint32_t*)ql,
                                          (uint32_t*)kh, (uint32_t*)kl,
                                          cp, sp, ROWS_, 3072, HID_);

    // #4 V transpose+split
    dim3 tv(32, 8);
    split_vt_kernel<<<dim3(S_ / 32, HD_ / 32, B_ * NKV_), tv>>>(vp, vh, vl);

    // #5 Flash attention
    dim3 gf(S_ / 128, NH_, B_);
    flash_hmma_kernel<<<gf, 256, FL_SMEM>>>(qh, ql, kh, kl, vh, vl,
                                            (uint32_t*)ath, (uint32_t*)atl);

    // #6 Output projection (fp32 out)
    dim3 go(2048 / 128, ROWS_ / 64);   // (16, 64)
    hgemm_kernel<0><<<go, 256, HG_SMEM>>>(ath, atl, owh, owl,
                                          nullptr, nullptr, nullptr, out,
                                          nullptr, nullptr, nullptr, nullptr,
                                          nullptr, nullptr, ROWS_, HID_,
                                          NH_ * HD_);
}

// round 17
// speedup vs baseline: 1.1185x; 1.0031x over previous
#include <cuda_runtime.h>
#include <cuda_bf16.h>
#include <math.h>
#include <math_constants.h>
#include <cstdint>

// Problem constants
#define B_   2
#define S_   2048
#define HID_ 2048
#define NH_  16
#define NKV_ 4
#define HD_  128
#define ROWS_ (B_ * S_)          // 4096

// Q pre-scale: 1/sqrt(128) * log2(e)
#define QSC ((float)(0.08838834764831845 * 1.4426950408889634))

// ---------------- scratch (device globals; no allocation allowed) ----------
__device__ float g_cos[S_ * 64];
__device__ float g_sin[S_ * 64];

// bf16 split operands
__device__ __nv_bfloat16 g_hs_h[ROWS_ * HID_];
__device__ __nv_bfloat16 g_hs_l[ROWS_ * HID_];
__device__ __nv_bfloat16 g_at_h[ROWS_ * HID_];
__device__ __nv_bfloat16 g_at_l[ROWS_ * HID_];
__device__ __nv_bfloat16 g_w3_h[3072 * 2048];  // [Q|K|V] weights, [N,K]
__device__ __nv_bfloat16 g_w3_l[3072 * 2048];
__device__ __nv_bfloat16 g_ow_h[2048 * 2048];
__device__ __nv_bfloat16 g_ow_l[2048 * 2048];

__device__ __nv_bfloat16 g_qh[B_ * NH_ * S_ * HD_];   // [b][h][s][d]
__device__ __nv_bfloat16 g_ql[B_ * NH_ * S_ * HD_];
__device__ __nv_bfloat16 g_kh[B_ * NKV_ * S_ * HD_];  // [b][kvh][s][d]
__device__ __nv_bfloat16 g_kl[B_ * NKV_ * S_ * HD_];
__device__ __nv_bfloat16 g_vh[B_ * NKV_ * HD_ * S_];  // [b][kvh][d][s]
__device__ __nv_bfloat16 g_vl[B_ * NKV_ * HD_ * S_];

// ====================== helpers =============================================
__device__ __forceinline__ uint32_t smem_u32(const void* p) {
    uint32_t r;
    asm("{ .reg .u64 t; cvta.to.shared.u64 t, %1; cvt.u32.u64 %0, t; }"
        : "=r"(r) : "l"(p));
    return r;
}

__device__ __forceinline__ void cp16(uint32_t dst, const void* src) {
    asm volatile("cp.async.cg.shared.global [%0], [%1], 16;"
                 :: "r"(dst), "l"(src) : "memory");
}

__device__ __forceinline__ float ex2(float x) {
    float r;
    asm("ex2.approx.f32 %0, %1;" : "=f"(r) : "f"(x));
    return r;
}

__device__ __forceinline__ void mma_bf16(float c[4], uint32_t a0, uint32_t a1,
                                         uint32_t a2, uint32_t a3,
                                         uint32_t b0, uint32_t b1) {
    asm volatile(
        "mma.sync.aligned.m16n8k16.row.col.f32.bf16.bf16.f32 "
        "{%0,%1,%2,%3}, {%4,%5,%6,%7}, {%8,%9}, {%0,%1,%2,%3};"
        : "+f"(c[0]), "+f"(c[1]), "+f"(c[2]), "+f"(c[3])
        : "r"(a0), "r"(a1), "r"(a2), "r"(a3), "r"(b0), "r"(b1));
}

__device__ __forceinline__ void ldsm4(uint32_t a[4], uint32_t addr) {
    asm volatile("ldmatrix.sync.aligned.m8n8.x4.shared.b16 {%0,%1,%2,%3}, [%4];"
                 : "=r"(a[0]), "=r"(a[1]), "=r"(a[2]), "=r"(a[3]) : "r"(addr));
}

__device__ __forceinline__ void split_pack(float x0, float x1,
                                           uint32_t& hi, uint32_t& lo) {
    uint32_t h;
    asm("cvt.rn.bf16x2.f32 %0, %1, %2;" : "=r"(h) : "f"(x1), "f"(x0));
    float h0 = __uint_as_float(h << 16);
    float h1 = __uint_as_float(h & 0xFFFF0000u);
    float r0 = x0 - h0, r1 = x1 - h1;
    uint32_t l;
    asm("cvt.rn.bf16x2.f32 %0, %1, %2;" : "=r"(l) : "f"(r1), "f"(r0));
    hi = h;
    lo = l;
}

// ================= HMMA split-bf16 GEMM (fused epilogues) ===================
// C[M,N] = A[M,K] @ Bt[N,K]^T. 3-stage cp.async pipeline, pitch 80B, 2 CTAs/SM.
// BM=64 BN=128 BK=32, 256 threads (8 warps 2x4), warp tile 32x32.
// MODE 0: fp32 out to C.
// MODE 3: fused QKV epilogue by n0: Q->OH/OL (rope+QSC+split),
//         K->OH2/OL2 (rope+split), V->VH/VL (split, TRANSPOSED [b][kvh][d][s]).
#define HG_P    80
#define HG_SA_L 5120
#define HG_SB_H 10240
#define HG_SB_L 20480
#define HG_STAGE 30720
#define HG_SMEM (3 * HG_STAGE)   // 92160 per CTA -> 2 CTAs/SM

template <int MODE>
__global__ __launch_bounds__(256, 2) void hgemm_kernel(
    const __nv_bfloat16* __restrict__ Ah, const __nv_bfloat16* __restrict__ Al,
    const __nv_bfloat16* __restrict__ Bh, const __nv_bfloat16* __restrict__ Bl,
    const float* __restrict__ qb, const float* __restrict__ kb,
    const float* __restrict__ vb, float* __restrict__ C,
    uint32_t* __restrict__ OH, uint32_t* __restrict__ OL,
    uint32_t* __restrict__ OH2, uint32_t* __restrict__ OL2,
    __nv_bfloat16* __restrict__ VH, __nv_bfloat16* __restrict__ VL,
    const float* __restrict__ cs, const float* __restrict__ sn,
    int M, int N, int K) {
    extern __shared__ __align__(16) char smc[];
    uint32_t sb = smem_u32(smc);
    int tid = threadIdx.x, wid = tid >> 5, lane = tid & 31;
    int warp_m = wid >> 2, warp_n = wid & 3;
    int m0 = blockIdx.y * 64, n0 = blockIdx.x * 128;
    int g = lane >> 2, t = lane & 3;

    int r8 = lane & 7, sel = lane >> 3;
    uint32_t aoff = (uint32_t)((warp_m * 32 + (sel & 1) * 8 + r8) * HG_P +
                               (sel >> 1) * 16);
    uint32_t boff = (uint32_t)((warp_n * 32 + ((lane >> 4) & 1) * 8 + r8) * HG_P +
                               ((lane >> 3) & 1) * 16);

    auto load_stage = [&](int k0, int stg) {
        uint32_t st = sb + stg * HG_STAGE;
        {
            int row = tid >> 2, seg = tid & 3;
            uint32_t so = row * HG_P + seg * 16;
            size_t ga = (size_t)(m0 + row) * K + k0 + seg * 8;
            cp16(st + so, Ah + ga);
            cp16(st + HG_SA_L + so, Al + ga);
        }
#pragma unroll
        for (int i = 0; i < 2; i++) {
            int idx = tid + i * 256;
            int row = idx >> 2, seg = idx & 3;
            uint32_t so = row * HG_P + seg * 16;
            size_t gb = (size_t)(n0 + row) * K + k0 + seg * 8;
            cp16(st + HG_SB_H + so, Bh + gb);
            cp16(st + HG_SB_L + so, Bl + gb);
        }
        asm volatile("cp.async.commit_group;" ::: "memory");
    };

    float acc[2][4][4];
#pragma unroll
    for (int i = 0; i < 2; i++)
#pragma unroll
        for (int j = 0; j < 4; j++)
#pragma unroll
            for (int x = 0; x < 4; x++) acc[i][j][x] = 0.0f;

    const int niter = K / 32;
    load_stage(0, 0);
    load_stage(32, 1);

    for (int it = 0; it < niter; it++) {
        if (it < niter - 1)
            asm volatile("cp.async.wait_group 1;" ::: "memory");
        else
            asm volatile("cp.async.wait_group 0;" ::: "memory");
        __syncthreads();
        int s3 = it % 3;
        uint32_t st = sb + s3 * HG_STAGE;

#pragma unroll
        for (int kc = 0; kc < 2; kc++) {
            uint32_t ah[2][4], al[2][4];
#pragma unroll
            for (int fm = 0; fm < 2; fm++) {
                ldsm4(ah[fm], st + aoff + fm * (16 * HG_P) + kc * 32);
                ldsm4(al[fm], st + HG_SA_L + aoff + fm * (16 * HG_P) + kc * 32);
            }
            uint32_t bh4[2][4], bl4[2][4];
#pragma unroll
            for (int fnp = 0; fnp < 2; fnp++) {
                uint32_t bo = boff + fnp * (16 * HG_P) + kc * 32;
                ldsm4(bh4[fnp], st + HG_SB_H + bo);
                ldsm4(bl4[fnp], st + HG_SB_L + bo);
            }
#pragma unroll
            for (int fm = 0; fm < 2; fm++)
#pragma unroll
                for (int fnp = 0; fnp < 2; fnp++) {
                    mma_bf16(acc[fm][2 * fnp], ah[fm][0], ah[fm][1], ah[fm][2],
                             ah[fm][3], bh4[fnp][0], bh4[fnp][1]);
                    mma_bf16(acc[fm][2 * fnp + 1], ah[fm][0], ah[fm][1],
                             ah[fm][2], ah[fm][3], bh4[fnp][2], bh4[fnp][3]);
                }
#pragma unroll
            for (int fm = 0; fm < 2; fm++)
#pragma unroll
                for (int fnp = 0; fnp < 2; fnp++) {
                    mma_bf16(acc[fm][2 * fnp], ah[fm][0], ah[fm][1], ah[fm][2],
                             ah[fm][3], bl4[fnp][0], bl4[fnp][1]);
                    mma_bf16(acc[fm][2 * fnp + 1], ah[fm][0], ah[fm][1],
                             ah[fm][2], ah[fm][3], bl4[fnp][2], bl4[fnp][3]);
                }
#pragma unroll
            for (int fm = 0; fm < 2; fm++)
#pragma unroll
                for (int fnp = 0; fnp < 2; fnp++) {
                    mma_bf16(acc[fm][2 * fnp], al[fm][0], al[fm][1], al[fm][2],
                             al[fm][3], bh4[fnp][0], bh4[fnp][1]);
                    mma_bf16(acc[fm][2 * fnp + 1], al[fm][0], al[fm][1],
                             al[fm][2], al[fm][3], bh4[fnp][2], bh4[fnp][3]);
                }
        }
        if (it + 2 < niter) load_stage((it + 2) * 32, (it + 2) % 3);
    }

    // epilogue
#pragma unroll
    for (int fm = 0; fm < 2; fm++) {
        int row0 = m0 + warp_m * 32 + fm * 16 + g;
#pragma unroll
        for (int fn = 0; fn < 4; fn++) {
            int col = n0 + warp_n * 32 + fn * 8 + 2 * t;
            if (MODE == 0) {
                float2 v0, v1;
                v0.x = acc[fm][fn][0];
                v0.y = acc[fm][fn][1];
                v1.x = acc[fm][fn][2];
                v1.y = acc[fm][fn][3];
                *(float2*)(C + (size_t)row0 * N + col) = v0;
                *(float2*)(C + (size_t)(row0 + 8) * N + col) = v1;
            } else if (n0 < 2048) {
                float2 bb = *(const float2*)(qb + col);
                float vx[2] = {acc[fm][fn][0] + bb.x, acc[fm][fn][2] + bb.x};
                float vy[2] = {acc[fm][fn][1] + bb.y, acc[fm][fn][3] + bb.y};
                int hh = col >> 7;
                int p = (col & 127) >> 1;
#pragma unroll
                for (int rr = 0; rr < 2; rr++) {
                    int row = row0 + rr * 8;
                    int s = row & (S_ - 1);
                    int bb_ = row >> 11;
                    float cv = cs[s * 64 + p];
                    float sv = sn[s * 64 + p];
                    float o1 = (vx[rr] * cv - vy[rr] * sv) * QSC;
                    float o2 = (vx[rr] * sv + vy[rr] * cv) * QSC;
                    uint32_t hi, lo;
                    split_pack(o1, o2, hi, lo);
                    size_t wi = (((size_t)bb_ * NH_ + hh) * S_ + s) * 64 + p;
                    OH[wi] = hi;
                    OL[wi] = lo;
                }
            } else if (n0 < 2560) {
                int c2 = col - 2048;
                float2 bb = *(const float2*)(kb + c2);
                float vx[2] = {acc[fm][fn][0] + bb.x, acc[fm][fn][2] + bb.x};
                float vy[2] = {acc[fm][fn][1] + bb.y, acc[fm][fn][3] + bb.y};
                int hh = c2 >> 7;
                int p = (c2 & 127) >> 1;
#pragma unroll
                for (int rr = 0; rr < 2; rr++) {
                    int row = row0 + rr * 8;
                    int s = row & (S_ - 1);
                    int bb_ = row >> 11;
                    float cv = cs[s * 64 + p];
                    float sv = sn[s * 64 + p];
                    float o1 = vx[rr] * cv - vy[rr] * sv;
                    float o2 = vx[rr] * sv + vy[rr] * cv;
                    uint32_t hi, lo;
                    split_pack(o1, o2, hi, lo);
                    size_t wi = (((size_t)bb_ * NKV_ + hh) * S_ + s) * 64 + p;
                    OH2[wi] = hi;
                    OL2[wi] = lo;
                }
            } else {
                // V epilogue: +bias, bf16 hi/lo split, TRANSPOSED write
                int c2 = col - 2560;           // [0,512)
                float2 bb = *(const float2*)(vb + c2);
                int kvh2 = c2 >> 7, d = c2 & 127;
                float vals[2][2] = {
                    {acc[fm][fn][0] + bb.x, acc[fm][fn][1] + bb.y},
                    {acc[fm][fn][2] + bb.x, acc[fm][fn][3] + bb.y}};
#pragma unroll
                for (int rr = 0; rr < 2; rr++) {
                    int row = row0 + rr * 8;
                    int s = row & (S_ - 1);
                    int b2 = row >> 11;
                    size_t base =
                        (((size_t)(b2 * NKV_ + kvh2)) * 128 + d) * (size_t)S_ + s;
#pragma unroll
                    for (int dd = 0; dd < 2; dd++) {
                        float v = vals[rr][dd];
                        __nv_bfloat16 hb = __float2bfloat16(v);
                        VH[base + (size_t)dd * S_] = hb;
                        VL[base + (size_t)dd * S_] =
                            __float2bfloat16(v - __bfloat162float(hb));
                    }
                }
            }
        }
    }
}

// ---------------- conversion kernels ----------------------------------------
__global__ void split_hs_rope_kernel(const float* __restrict__ x,
                                     __nv_bfloat16* __restrict__ h,
                                     __nv_bfloat16* __restrict__ l, int n4,
                                     float* __restrict__ cs,
                                     float* __restrict__ sn) {
    int i = blockIdx.x * blockDim.x + threadIdx.x;
    if (blockIdx.x < 512) {
        int idx = i;
        int s = idx >> 6;
        int p = idx & 63;
        double freq = exp(-((double)(2 * p) / (double)HD_) * log(10000.0));
        double ang = (double)s * freq;
        double sv, cv;
        sincos(ang, &sv, &cv);
        cs[idx] = (float)cv;
        sn[idx] = (float)sv;
    }
    if (i >= n4) return;
    float4 v = ((const float4*)x)[i];
    uint32_t h0, l0, h1, l1;
    split_pack(v.x, v.y, h0, l0);
    split_pack(v.z, v.w, h1, l1);
    ((uint32_t*)h)[i * 2 + 0] = h0;
    ((uint32_t*)h)[i * 2 + 1] = h1;
    ((uint32_t*)l)[i * 2 + 0] = l0;
    ((uint32_t*)l)[i * 2 + 1] = l1;
}

// Fused weight transpose for ALL weights:
// rows [0,3072)   -> W3 (Q|K|V) [3072][2048]
// rows [3072,5120) -> OW [2048][2048]
__global__ void transpose_all_kernel(const float* __restrict__ qw,
                                     const float* __restrict__ kw,
                                     const float* __restrict__ vw,
                                     const float* __restrict__ ow,
                                     __nv_bfloat16* __restrict__ W3h,
                                     __nv_bfloat16* __restrict__ W3l,
                                     __nv_bfloat16* __restrict__ OWh,
                                     __nv_bfloat16* __restrict__ OWl) {
    __shared__ float tshm[32][33];
    int colg = blockIdx.x * 32;        // [0, 5120)
    int k0 = blockIdx.y * 32;
    const float* W;
    __nv_bfloat16 *Th, *Tl;
    int N, n0, obase;
    if (colg < 2048) {
        W = qw; N = 2048; n0 = colg; obase = colg; Th = W3h; Tl = W3l;
    } else if (colg < 2560) {
        W = kw; N = 512; n0 = colg - 2048; obase = colg; Th = W3h; Tl = W3l;
    } else if (colg < 3072) {
        W = vw; N = 512; n0 = colg - 2560; obase = colg; Th = W3h; Tl = W3l;
    } else {
        W = ow; N = 2048; n0 = colg - 3072; obase = colg - 3072; Th = OWh; Tl = OWl;
    }
    int tx = threadIdx.x, ty = threadIdx.y;  // (32,8)
#pragma unroll
    for (int i = 0; i < 32; i += 8)
        tshm[ty + i][tx] = W[(size_t)(k0 + ty + i) * N + n0 + tx];
    __syncthreads();
#pragma unroll
    for (int i = 0; i < 32; i += 8) {
        int n = obase + ty + i, k = k0 + tx;
        float v = tshm[tx][ty + i];
        __nv_bfloat16 hb = __float2bfloat16(v);
        Th[(size_t)n * 2048 + k] = hb;
        Tl[(size_t)n * 2048 + k] = __float2bfloat16(v - __bfloat162float(hb));
    }
}

// ---------------- Flash attention (HMMA, bf16 3-term split, ldmatrix) -------
#define FL_QL 0
#define FL_QH 34816
#define FL_STG 69632
#define FL_STG_BYTES 71680
#define FL_KL 17408
#define FL_VH 34816
#define FL_VL 53248
#define FL_SMEM (FL_STG + 2 * FL_STG_BYTES)
#define NEGINF_F (__int_as_float(0xff800000))

__global__ __launch_bounds__(256, 1) void flash_hmma_kernel(
    const __nv_bfloat16* __restrict__ qhg, const __nv_bfloat16* __restrict__ qlg,
    const __nv_bfloat16* __restrict__ khg, const __nv_bfloat16* __restrict__ klg,
    const __nv_bfloat16* __restrict__ vhg, const __nv_bfloat16* __restrict__ vlg,
    uint32_t* __restrict__ outH, uint32_t* __restrict__ outL) {
    int qt = gridDim.x - 1 - blockIdx.x;
    int h = blockIdx.y;
    int b = blockIdx.z;
    int kvh = h >> 2;
    int bh = b * NH_ + h;
    int bk = b * NKV_ + kvh;

    extern __shared__ __align__(16) char sm[];
    uint32_t sbase = smem_u32(sm);

    int tid = threadIdx.x;
    int w = tid >> 5, lane = tid & 31;
    int g = lane >> 2, t = lane & 3;
    int r8 = lane & 7, sel = lane >> 3;

    uint32_t qoff = (uint32_t)((w * 16 + (sel & 1) * 8 + r8) * 272 +
                               (sel >> 1) * 16);
    uint32_t koff = (uint32_t)((((lane >> 4) & 1) * 8 + r8) * 272 +
                               ((lane >> 3) & 1) * 16);
    uint32_t voff = (uint32_t)((((lane >> 4) & 1) * 8 + r8) * 144 +
                               ((lane >> 3) & 1) * 16);

    {
        const __nv_bfloat16* qh_g = qhg + ((size_t)bh * S_ + qt * 128) * 128;
        const __nv_bfloat16* ql_g = qlg + ((size_t)bh * S_ + qt * 128) * 128;
#pragma unroll
        for (int i = 0; i < 8; i++) {
            int c = tid + i * 256;
            int row = c >> 4, c16 = c & 15;
            cp16(sbase + FL_QH + row * 272 + c16 * 16, qh_g + row * 128 + c16 * 8);
            cp16(sbase + FL_QL + row * 272 + c16 * 16, ql_g + row * 128 + c16 * 8);
        }
        asm volatile("cp.async.commit_group;" ::: "memory");
    }

    const __nv_bfloat16* kh_b = khg + (size_t)bk * S_ * 128;
    const __nv_bfloat16* kl_b = klg + (size_t)bk * S_ * 128;
    const __nv_bfloat16* vh_b = vhg + (size_t)bk * 128 * S_;
    const __nv_bfloat16* vl_b = vlg + (size_t)bk * 128 * S_;

    auto load_kv = [&](int jt, int stg) {
        uint32_t sb = sbase + FL_STG + stg * FL_STG_BYTES;
#pragma unroll
        for (int i = 0; i < 4; i++) {
            int c = tid + i * 256;
            int row = c >> 4, c16 = c & 15;
            size_t go = ((size_t)(jt * 64 + row)) * 128 + c16 * 8;
            cp16(sb + row * 272 + c16 * 16, kh_b + go);
            cp16(sb + FL_KL + row * 272 + c16 * 16, kl_b + go);
        }
#pragma unroll
        for (int i = 0; i < 4; i++) {
            int c = tid + i * 256;
            int row = c >> 3, c8 = c & 7;
            size_t go = (size_t)row * S_ + jt * 64 + c8 * 8;
            cp16(sb + FL_VH + row * 144 + c8 * 16, vh_b + go);
            cp16(sb + FL_VL + row * 144 + c8 * 16, vl_b + go);
        }
        asm volatile("cp.async.commit_group;" ::: "memory");
    };

    int njt = 2 * qt + 2;
    load_kv(0, 0);
    load_kv(1, 1);
    asm volatile("cp.async.wait_group 2;" ::: "memory");
    __syncthreads();

    uint32_t qfh[8][4], qfl[8][4];
#pragma unroll
    for (int kk = 0; kk < 8; kk++) {
        ldsm4(qfh[kk], sbase + FL_QH + qoff + kk * 32);
        ldsm4(qfl[kk], sbase + FL_QL + qoff + kk * 32);
    }

    float o_[16][4];
#pragma unroll
    for (int n = 0; n < 16; n++)
#pragma unroll
        for (int j = 0; j < 4; j++) o_[n][j] = 0.0f;
    float m0 = NEGINF_F, m1 = NEGINF_F, l0 = 0.0f, l1 = 0.0f;

    for (int jt = 0; jt < njt; jt++) {
        if (jt < njt - 1)
            asm volatile("cp.async.wait_group 1;" ::: "memory");
        else
            asm volatile("cp.async.wait_group 0;" ::: "memory");
        __syncthreads();

        uint32_t kst = sbase + FL_STG + (jt & 1) * FL_STG_BYTES;

        float s[8][4];
#pragma unroll
        for (int j = 0; j < 8; j++)
#pragma unroll
            for (int x = 0; x < 4; x++) s[j][x] = 0.0f;

        for (int kk = 0; kk < 8; kk++) {
#pragma unroll
            for (int jp = 0; jp < 4; jp++) {
                uint32_t kb[4], lb[4];
                uint32_t ko = koff + jp * (16 * 272) + kk * 32;
                ldsm4(kb, kst + ko);
                ldsm4(lb, kst + FL_KL + ko);
                mma_bf16(s[2 * jp], qfh[kk][0], qfh[kk][1], qfh[kk][2],
                         qfh[kk][3], kb[0], kb[1]);
                mma_bf16(s[2 * jp + 1], qfh[kk][0], qfh[kk][1], qfh[kk][2],
                         qfh[kk][3], kb[2], kb[3]);
                mma_bf16(s[2 * jp], qfh[kk][0], qfh[kk][1], qfh[kk][2],
                         qfh[kk][3], lb[0], lb[1]);
                mma_bf16(s[2 * jp + 1], qfh[kk][0], qfh[kk][1], qfh[kk][2],
                         qfh[kk][3], lb[2], lb[3]);
                mma_bf16(s[2 * jp], qfl[kk][0], qfl[kk][1], qfl[kk][2],
                         qfl[kk][3], kb[0], kb[1]);
                mma_bf16(s[2 * jp + 1], qfl[kk][0], qfl[kk][1], qfl[kk][2],
                         qfl[kk][3], kb[2], kb[3]);
            }
        }

        if (jt * 64 + 63 > qt * 128 + w * 16) {
            int row0 = qt * 128 + w * 16 + g;
            int row1 = row0 + 8;
#pragma unroll
            for (int j = 0; j < 8; j++) {
                int col = jt * 64 + 8 * j + 2 * t;
                if (col > row0) s[j][0] = NEGINF_F;
                if (col + 1 > row0) s[j][1] = NEGINF_F;
                if (col > row1) s[j][2] = NEGINF_F;
                if (col + 1 > row1) s[j][3] = NEGINF_F;
            }
        }

        float mx0 = NEGINF_F, mx1 = NEGINF_F;
#pragma unroll
        for (int j = 0; j < 8; j++) {
            mx0 = fmaxf(mx0, fmaxf(s[j][0], s[j][1]));
            mx1 = fmaxf(mx1, fmaxf(s[j][2], s[j][3]));
        }
        mx0 = fmaxf(mx0, __shfl_xor_sync(0xffffffff, mx0, 1));
        mx0 = fmaxf(mx0, __shfl_xor_sync(0xffffffff, mx0, 2));
        mx1 = fmaxf(mx1, __shfl_xor_sync(0xffffffff, mx1, 1));
        mx1 = fmaxf(mx1, __shfl_xor_sync(0xffffffff, mx1, 2));
        float mn0 = fmaxf(m0, mx0), mn1 = fmaxf(m1, mx1);
        float a0 = ex2(m0 - mn0), a1 = ex2(m1 - mn1);
        m0 = mn0;
        m1 = mn1;
        float sum0 = 0.0f, sum1 = 0.0f;
#pragma unroll
        for (int j = 0; j < 8; j++) {
            s[j][0] = ex2(s[j][0] - mn0);
            s[j][1] = ex2(s[j][1] - mn0);
            s[j][2] = ex2(s[j][2] - mn1);
            s[j][3] = ex2(s[j][3] - mn1);
            sum0 += s[j][0] + s[j][1];
            sum1 += s[j][2] + s[j][3];
        }
        sum0 += __shfl_xor_sync(0xffffffff, sum0, 1);
        sum0 += __shfl_xor_sync(0xffffffff, sum0, 2);
        sum1 += __shfl_xor_sync(0xffffffff, sum1, 1);
        sum1 += __shfl_xor_sync(0xffffffff, sum1, 2);
        l0 = l0 * a0 + sum0;
        l1 = l1 * a1 + sum1;
#pragma unroll
        for (int n = 0; n < 16; n++) {
            o_[n][0] *= a0;
            o_[n][1] *= a0;
            o_[n][2] *= a1;
            o_[n][3] *= a1;
        }

#pragma unroll
        for (int kk = 0; kk < 4; kk++) {
            uint32_t pa0, pa1, pa2, pa3, la0, la1, la2, la3;
            split_pack(s[2 * kk][0], s[2 * kk][1], pa0, la0);
            split_pack(s[2 * kk][2], s[2 * kk][3], pa1, la1);
            split_pack(s[2 * kk + 1][0], s[2 * kk + 1][1], pa2, la2);
            split_pack(s[2 * kk + 1][2], s[2 * kk + 1][3], pa3, la3);
#pragma unroll
            for (int np = 0; np < 8; np++) {
                uint32_t vb[4], wb[4];
                uint32_t vo = voff + np * (16 * 144) + kk * 32;
                ldsm4(vb, kst + FL_VH + vo);
                ldsm4(wb, kst + FL_VL + vo);
                mma_bf16(o_[2 * np], pa0, pa1, pa2, pa3, vb[0], vb[1]);
                mma_bf16(o_[2 * np + 1], pa0, pa1, pa2, pa3, vb[2], vb[3]);
                mma_bf16(o_[2 * np], pa0, pa1, pa2, pa3, wb[0], wb[1]);
                mma_bf16(o_[2 * np + 1], pa0, pa1, pa2, pa3, wb[2], wb[3]);
                mma_bf16(o_[2 * np], la0, la1, la2, la3, vb[0], vb[1]);
                mma_bf16(o_[2 * np + 1], la0, la1, la2, la3, vb[2], vb[3]);
            }
        }

        __syncthreads();
        if (jt + 2 < njt) load_kv(jt + 2, jt & 1);
    }

    float inv0 = 1.0f / l0, inv1 = 1.0f / l1;
    int row0 = qt * 128 + w * 16 + g;
    int row1 = row0 + 8;
#pragma unroll
    for (int n = 0; n < 16; n++) {
        int col = h * 128 + 8 * n + 2 * t;
        uint32_t hi0, lo0, hi1, lo1;
        split_pack(o_[n][0] * inv0, o_[n][1] * inv0, hi0, lo0);
        split_pack(o_[n][2] * inv1, o_[n][3] * inv1, hi1, lo1);
        size_t w0 = ((size_t)(b * S_ + row0) * 2048 + col) >> 1;
        size_t w1 = ((size_t)(b * S_ + row1) * 2048 + col) >> 1;
        outH[w0] = hi0;
        outL[w0] = lo0;
        outH[w1] = hi1;
        outL[w1] = lo1;
    }
}

// ---------------- launch ----------------------------------------------------
extern "C" void kernel_launch(void* const* d_in, const int* in_sizes, int n_in,
                              void* d_out, int out_size) {
    const float* hs  = (const float*)d_in[0];
    const float* q_w = (const float*)d_in[1];
    const float* q_b = (const float*)d_in[2];
    const float* k_w = (const float*)d_in[3];
    const float* k_b = (const float*)d_in[4];
    const float* v_w = (const float*)d_in[5];
    const float* v_b = (const float*)d_in[6];
    const float* o_w = (const float*)d_in[7];
    float* out = (float*)d_out;

    float *cp, *sp;
    cudaGetSymbolAddress((void**)&cp, g_cos);
    cudaGetSymbolAddress((void**)&sp, g_sin);

    __nv_bfloat16 *hsh, *hsl, *ath, *atl, *w3h, *w3l, *owh, *owl;
    cudaGetSymbolAddress((void**)&hsh, g_hs_h);
    cudaGetSymbolAddress((void**)&hsl, g_hs_l);
    cudaGetSymbolAddress((void**)&ath, g_at_h);
    cudaGetSymbolAddress((void**)&atl, g_at_l);
    cudaGetSymbolAddress((void**)&w3h, g_w3_h);
    cudaGetSymbolAddress((void**)&w3l, g_w3_l);
    cudaGetSymbolAddress((void**)&owh, g_ow_h);
    cudaGetSymbolAddress((void**)&owl, g_ow_l);

    __nv_bfloat16 *qh, *ql, *kh, *kl, *vh, *vl;
    cudaGetSymbolAddress((void**)&qh, g_qh);
    cudaGetSymbolAddress((void**)&ql, g_ql);
    cudaGetSymbolAddress((void**)&kh, g_kh);
    cudaGetSymbolAddress((void**)&kl, g_kl);
    cudaGetSymbolAddress((void**)&vh, g_vh);
    cudaGetSymbolAddress((void**)&vl, g_vl);

    cudaFuncSetAttribute(hgemm_kernel<0>,
                         cudaFuncAttributeMaxDynamicSharedMemorySize, HG_SMEM);
    cudaFuncSetAttribute(hgemm_kernel<3>,
                         cudaFuncAttributeMaxDynamicSharedMemorySize, HG_SMEM);
    cudaFuncSetAttribute(flash_hmma_kernel,
                         cudaFuncAttributeMaxDynamicSharedMemorySize, FL_SMEM);

    dim3 tb(32, 8);

    // #1 activation split + RoPE table
    int n4_hs = (ROWS_ * HID_) / 4;
    split_hs_rope_kernel<<<(n4_hs + 255) / 256, 256>>>(hs, hsh, hsl, n4_hs, cp, sp);

    // #2 ALL weight transposes in one launch (Q|K|V -> W3, O -> OW)
    transpose_all_kernel<<<dim3(160, 64), tb>>>(q_w, k_w, v_w, o_w,
                                                w3h, w3l, owh, owl);

    // #3 fused QKV projection (V epilogue writes transposed bf16 hi/lo)
    dim3 g3(3072 / 128, ROWS_ / 64);   // (24, 64) = 1536 CTAs
    hgemm_kernel<3><<<g3, 256, HG_SMEM>>>(hsh, hsl, w3h, w3l,
                                          q_b, k_b, v_b, nullptr,
                                          (uint32_t*)qh, (uint32_t*)ql,
                                          (uint32_t*)kh, (uint32_t*)kl,
                                          vh, vl,
                                          cp, sp, ROWS_, 3072, HID_);

    // #4 Flash attention (PROFILED)
    dim3 gf(S_ / 128, NH_, B_);
    flash_hmma_kernel<<<gf, 256, FL_SMEM>>>(qh, ql, kh, kl, vh, vl,
                                            (uint32_t*)ath, (uint32_t*)atl);

    // #5 Output projection (fp32 out)
    dim3 go(2048 / 128, ROWS_ / 64);   // (16, 64)
    hgemm_kernel<0><<<go, 256, HG_SMEM>>>(ath, atl, owh, owl,
                                          nullptr, nullptr, nullptr, out,
                                          nullptr, nullptr, nullptr, nullptr,
                                          nullptr, nullptr,
                                          nullptr, nullptr, ROWS_, HID_,
                                          NH_ * HD_);
}